// round 4
// baseline (speedup 1.0000x reference)
#include <cuda_runtime.h>
#include <cuda_fp16.h>
#include <mma.h>

using namespace nvcuda;

#define N_ATOMS  100000
#define N_PAIRS  1600000

// ---------------- scratch (device globals; no allocation allowed) ----------
// g_uv interleaved: g_uv[atom*100 + 2k] = u_k, [.. +1] = v_k  (fp16, 20MB)
__device__ __half g_uv [(size_t)N_ATOMS * 100];
__device__ __half g_AA [(size_t)N_ATOMS * 50];
__device__ float  g_PA [(size_t)N_ATOMS * 50];

__device__ __forceinline__ float frelu(float x) { return fmaxf(x, 0.f); }

// ============================================================================
// K1: per-atom GEMM. X = af(128x80pad) @ W(80x160) -> AA | u | v.  Zero g_PA.
// ============================================================================
struct K1S {
    union {
        struct { __half Af[128 * 80]; __half Wt[80 * 160]; };
        float C[128 * 160];
    };
    float bAA[64];
};

__global__ __launch_bounds__(512) void k1_atoms(
    const float* __restrict__ af,
    const float* __restrict__ W_AA, const float* __restrict__ b_AA,
    const float* __restrict__ W_AP)
{
    extern __shared__ char smem_raw[];
    K1S& S = *reinterpret_cast<K1S*>(smem_raw);
    const int tid  = threadIdx.x;
    const int base = blockIdx.x * 128;

    for (int idx = tid; idx < 80 * 160; idx += 512) {
        int d = idx / 160, n = idx - d * 160;
        float w = 0.f;
        if (d < 75) {
            if      (n < 50)  w = W_AA[d * 50 + n];
            else if (n < 100) w = W_AP[d * 50 + (n - 50)];
            else if (n < 150) w = W_AP[(75 + d) * 50 + (n - 100)];
        }
        S.Wt[idx] = __float2half(w);
    }
    for (int idx = tid; idx < 128 * 80; idx += 512) {
        int m = idx / 80, d = idx - m * 80;
        int ga = base + m;
        float v = (ga < N_ATOMS && d < 75) ? af[(size_t)ga * 75 + d] : 0.f;
        S.Af[idx] = __float2half(v);
    }
    if (tid < 50) S.bAA[tid] = b_AA[tid];
    for (int idx = tid; idx < 128 * 50; idx += 512) {
        int ga = base + idx / 50;
        if (ga < N_ATOMS) g_PA[(size_t)ga * 50 + (idx % 50)] = 0.f;
    }
    __syncthreads();

    const int warp = tid >> 5;
    const int mt = warp >> 1;
    const int nb = (warp & 1) * 5;

    wmma::fragment<wmma::accumulator, 16, 16, 16, float> acc[5];
    #pragma unroll
    for (int q = 0; q < 5; q++) wmma::fill_fragment(acc[q], 0.f);
    #pragma unroll
    for (int k = 0; k < 5; k++) {
        wmma::fragment<wmma::matrix_a, 16, 16, 16, __half, wmma::row_major> a;
        wmma::load_matrix_sync(a, S.Af + mt * 16 * 80 + k * 16, 80);
        #pragma unroll
        for (int q = 0; q < 5; q++) {
            wmma::fragment<wmma::matrix_b, 16, 16, 16, __half, wmma::row_major> b;
            wmma::load_matrix_sync(b, S.Wt + k * 16 * 160 + (nb + q) * 16, 160);
            wmma::mma_sync(acc[q], a, b, acc[q]);
        }
    }
    __syncthreads();
    #pragma unroll
    for (int q = 0; q < 5; q++)
        wmma::store_matrix_sync(S.C + mt * 16 * 160 + (nb + q) * 16, acc[q], 160,
                                wmma::mem_row_major);
    __syncthreads();

    // AA -> fp16 (half2 writes) ; (u,v) -> interleaved fp16
    for (int idx = tid; idx < 128 * 25; idx += 512) {
        int m = idx / 25, q = idx - m * 25;
        int ga = base + m;
        if (ga >= N_ATOMS) continue;
        float lo = frelu(S.C[m * 160 + 2 * q]     + S.bAA[2 * q]);
        float hi = frelu(S.C[m * 160 + 2 * q + 1] + S.bAA[2 * q + 1]);
        ((__half2*)g_AA)[(size_t)ga * 25 + q] = __floats2half2_rn(lo, hi);
    }
    for (int idx = tid; idx < 128 * 50; idx += 512) {
        int m = idx / 50, n = idx - m * 50;
        int ga = base + m;
        if (ga >= N_ATOMS) continue;
        float u = S.C[m * 160 + 50 + n];
        float v = S.C[m * 160 + 100 + n];
        ((__half2*)g_uv)[(size_t)ga * 50 + n] = __floats2half2_rn(u, v);
    }
}

// ============================================================================
// K2: fused pair kernel. 256 pairs/block, 1024 threads, 1 block/SM (149KB).
//  W1 : pfh(256x16, ones-col) @ Wc(16x128) -> D = [relu(PA+b) | relu(PP+b)]
//       (fp16 acc, bias folded, relu on fragment)
//  G  : s[k]=relu(u_i+v_j+b)+relu(u_j+v_i+b) -> T[:,0:50] (L2 half2 gathers)
//  PPc: D PP block -> T[:,50:100]
//  PA : run-compressed segmented atomicAdd from D PA block
//  M  : T(256x112) @ Wp(112x64, b_P folded via ones-col 100) -> C
//  E  : outP = relu(C)
// ============================================================================
struct K2S {
    __half T[256 * 112];                                // 57344
    union { __half D[256 * 128]; float C[256 * 64]; };  // 65536
    __half pfh[256 * 16];                               // 8192
    __half Wc [16 * 128];                               // 4096
    __half Wp [112 * 64];                               // 14336
    float  bAP[64];
    int    ii[256], jj[256], seg[256];
};

__global__ __launch_bounds__(1024) void k2_pairs(
    const float* __restrict__ pair_features,
    const int*   __restrict__ pair_split,
    const int*   __restrict__ atom_to_pair,
    const float* __restrict__ W_PA, const float* __restrict__ b_PA,
    const float* __restrict__ W_PP, const float* __restrict__ b_PP,
    const float* __restrict__ W_P,  const float* __restrict__ b_P,
    const float* __restrict__ b_AP,
    float* __restrict__ outP)
{
    extern __shared__ char smem_raw[];
    K2S& S = *reinterpret_cast<K2S*>(smem_raw);
    const int tid  = threadIdx.x;
    const int base = blockIdx.x * 256;           // N_PAIRS % 256 == 0

    // ---- stage ----
    for (int idx = tid; idx < 256 * 16; idx += 1024) {
        int p = idx >> 4, d = idx & 15;
        float v = (d < 14) ? pair_features[(size_t)(base + p) * 14 + d]
                           : (d == 14 ? 1.f : 0.f);
        S.pfh[idx] = __float2half(v);
    }
    for (int idx = tid; idx < 16 * 128; idx += 1024) {
        int d = idx >> 7, n = idx & 127;
        float w = 0.f;
        if (d < 14) {
            if      (n < 50)              w = W_PA[d * 50 + n];
            else if (n >= 64 && n < 114)  w = W_PP[d * 50 + (n - 64)];
        } else if (d == 14) {
            if      (n < 50)              w = b_PA[n];
            else if (n >= 64 && n < 114)  w = b_PP[n - 64];
        }
        S.Wc[idx] = __float2half(w);
    }
    for (int idx = tid; idx < 112 * 64; idx += 1024) {
        int k = idx >> 6, n = idx & 63;
        float w = 0.f;
        if (n < 50) {
            if      (k < 100)  w = W_P[k * 50 + n];
            else if (k == 100) w = b_P[n];
        }
        S.Wp[idx] = __float2half(w);
    }
    if (tid < 64) S.bAP[tid] = (tid < 50) ? b_AP[tid] : 0.f;
    if (tid < 256) {
        int2 p2 = ((const int2*)atom_to_pair)[base + tid];
        S.ii[tid] = p2.x;
        S.jj[tid] = p2.y;
        S.seg[tid] = pair_split[base + tid];
    }
    // T cols 100..111: col 100 = 1 (b_P fold), rest 0
    for (int idx = tid; idx < 256 * 6; idx += 1024) {
        int p = idx / 6, q = idx - p * 6;
        ((__half2*)(S.T + p * 112 + 100))[q] =
            (q == 0) ? __floats2half2_rn(1.f, 0.f) : __floats2half2_rn(0.f, 0.f);
    }
    __syncthreads();

    // ---- W1: pfh @ Wc -> D, relu on fragment (bias folded) ----
    {
        const int warp = tid >> 5;               // 0..31
        const int mt = warp >> 1;                // 0..15
        const int nb = (warp & 1) * 4;           // 0 or 4
        wmma::fragment<wmma::matrix_a, 16, 16, 16, __half, wmma::row_major> a;
        wmma::load_matrix_sync(a, S.pfh + mt * 16 * 16, 16);
        const __half h0 = __float2half(0.f);
        #pragma unroll
        for (int q = 0; q < 4; q++) {
            wmma::fragment<wmma::accumulator, 16, 16, 16, __half> c;
            wmma::fill_fragment(c, h0);
            wmma::fragment<wmma::matrix_b, 16, 16, 16, __half, wmma::row_major> b;
            wmma::load_matrix_sync(b, S.Wc + (nb + q) * 16, 128);
            wmma::mma_sync(c, a, b, c);
            #pragma unroll
            for (int e = 0; e < c.num_elements; e++) c.x[e] = __hmax(c.x[e], h0);
            wmma::store_matrix_sync(S.D + mt * 16 * 128 + (nb + q) * 16, c, 128,
                                    wmma::mem_row_major);
        }
    }
    __syncthreads();

    // ---- G: symmetrized AP -> T[:,0:50]  (16 threads per pair, 4 passes) ----
    {
        const int t = tid & 15;
        #pragma unroll
        for (int pass = 0; pass < 4; pass++) {
            const int p = pass * 64 + (tid >> 4);
            const int i = S.ii[p], j = S.jj[p];
            const __half2* ri = (const __half2*)g_uv + (size_t)i * 50;
            const __half2* rj = (const __half2*)g_uv + (size_t)j * 50;
            #pragma unroll
            for (int q = 0; q < 3; q++) {
                int k = t + q * 16;
                __half2 a = __ldg(ri + k), b = __ldg(rj + k);
                float ui = __low2float(a), vi = __high2float(a);
                float uj = __low2float(b), vj = __high2float(b);
                float bb = S.bAP[k];
                S.T[p * 112 + k] =
                    __float2half(frelu(ui + vj + bb) + frelu(uj + vi + bb));
            }
            if (t < 2) {
                int k = 48 + t;
                __half2 a = __ldg(ri + k), b = __ldg(rj + k);
                float ui = __low2float(a), vi = __high2float(a);
                float uj = __low2float(b), vj = __high2float(b);
                float bb = S.bAP[k];
                S.T[p * 112 + k] =
                    __float2half(frelu(ui + vj + bb) + frelu(uj + vi + bb));
            }
        }
    }

    // ---- PP copy: D[:,64:114] -> T[:,50:100] (half2) ----
    for (int idx = tid; idx < 256 * 25; idx += 1024) {
        int p = idx / 25, q = idx - p * 25;
        ((__half2*)(S.T + p * 112 + 50))[q] = ((__half2*)(S.D + p * 128 + 64))[q];
    }

    // ---- PA: segmented reduction from D[:,0:50] (already relu'd) ----
    {
        const int col = tid & 63, chunk = tid >> 6;   // 16 chunks x 16 rows
        if (col < 50) {
            const int r0 = chunk * 16;
            float acc = 0.f;
            int cur = S.seg[r0];
            #pragma unroll 4
            for (int r = r0; r < r0 + 16; r++) {
                float v = __half2float(S.D[r * 128 + col]);
                int sg = S.seg[r];
                if (sg != cur) {
                    atomicAdd(&g_PA[(size_t)cur * 50 + col], acc);
                    acc = 0.f; cur = sg;
                }
                acc += v;
            }
            atomicAdd(&g_PA[(size_t)cur * 50 + col], acc);
        }
    }
    __syncthreads();

    // ---- M: T @ Wp -> C (overwrites D; all D reads done) ----
    {
        const int warp = tid >> 5;
        const int mt = warp >> 1;
        const int nb = (warp & 1) * 2;
        wmma::fragment<wmma::accumulator, 16, 16, 16, float> acc[2];
        #pragma unroll
        for (int q = 0; q < 2; q++) wmma::fill_fragment(acc[q], 0.f);
        #pragma unroll
        for (int k = 0; k < 7; k++) {
            wmma::fragment<wmma::matrix_a, 16, 16, 16, __half, wmma::row_major> a;
            wmma::load_matrix_sync(a, S.T + mt * 16 * 112 + k * 16, 112);
            #pragma unroll
            for (int q = 0; q < 2; q++) {
                wmma::fragment<wmma::matrix_b, 16, 16, 16, __half, wmma::row_major> b;
                wmma::load_matrix_sync(b, S.Wp + k * 16 * 64 + (nb + q) * 16, 64);
                wmma::mma_sync(acc[q], a, b, acc[q]);
            }
        }
        #pragma unroll
        for (int q = 0; q < 2; q++)
            wmma::store_matrix_sync(S.C + mt * 16 * 64 + (nb + q) * 16, acc[q], 64,
                                    wmma::mem_row_major);
    }
    __syncthreads();

    // ---- E: outP = relu(C)  (b_P folded into GEMM) ----
    for (int idx = tid; idx < 256 * 50; idx += 1024) {
        int p = idx / 50, n = idx - p * 50;
        outP[(size_t)(base + p) * 50 + n] = frelu(S.C[p * 64 + n]);
    }
}

// ============================================================================
// K3: atom output GEMM. [AA|PA](256x112pad) @ W_A(112x64pad) -> A.
// ============================================================================
struct K3S {
    union {
        __half X[256 * 112];
        float  C[256 * 64];
    };
    __half W[112 * 64];
    float  bA[64];
};

__global__ __launch_bounds__(512) void k3_atomsout(
    const float* __restrict__ W_A, const float* __restrict__ b_A,
    float* __restrict__ outA)
{
    extern __shared__ char smem_raw[];
    K3S& S = *reinterpret_cast<K3S*>(smem_raw);
    const int tid  = threadIdx.x;
    const int base = blockIdx.x * 256;

    for (int idx = tid; idx < 256 * 112; idx += 512) {
        int m = idx / 112, k = idx - m * 112;
        int ga = base + m;
        __half v = __float2half(0.f);
        if (ga < N_ATOMS) {
            if      (k < 50)  v = g_AA[(size_t)ga * 50 + k];
            else if (k < 100) v = __float2half(g_PA[(size_t)ga * 50 + (k - 50)]);
        }
        S.X[idx] = v;
    }
    for (int idx = tid; idx < 112 * 64; idx += 512) {
        int k = idx / 64, n = idx - k * 64;
        float w = (k < 100 && n < 50) ? W_A[k * 50 + n] : 0.f;
        S.W[idx] = __float2half(w);
    }
    if (tid < 64) S.bA[tid] = (tid < 50) ? b_A[tid] : 0.f;
    __syncthreads();

    {
        const int mt = tid >> 5;
        wmma::fragment<wmma::accumulator, 16, 16, 16, float> acc[4];
        #pragma unroll
        for (int q = 0; q < 4; q++) wmma::fill_fragment(acc[q], 0.f);
        #pragma unroll
        for (int k = 0; k < 7; k++) {
            wmma::fragment<wmma::matrix_a, 16, 16, 16, __half, wmma::row_major> a;
            wmma::load_matrix_sync(a, S.X + mt * 16 * 112 + k * 16, 112);
            #pragma unroll
            for (int q = 0; q < 4; q++) {
                wmma::fragment<wmma::matrix_b, 16, 16, 16, __half, wmma::row_major> b;
                wmma::load_matrix_sync(b, S.W + k * 16 * 64 + q * 16, 64);
                wmma::mma_sync(acc[q], a, b, acc[q]);
            }
        }
        __syncthreads();
        #pragma unroll
        for (int q = 0; q < 4; q++)
            wmma::store_matrix_sync(S.C + mt * 16 * 64 + q * 16, acc[q], 64,
                                    wmma::mem_row_major);
    }
    __syncthreads();

    for (int idx = tid; idx < 256 * 50; idx += 512) {
        int m = idx / 50, n = idx - m * 50;
        int ga = base + m;
        if (ga < N_ATOMS)
            outA[(size_t)ga * 50 + n] = frelu(S.C[m * 64 + n] + S.bA[n]);
    }
}

// ============================================================================
extern "C" void kernel_launch(void* const* d_in, const int* in_sizes, int n_in,
                              void* d_out, int out_size) {
    const float* atom_features = (const float*)d_in[0];
    const float* pair_features = (const float*)d_in[1];
    const int*   pair_split    = (const int*)  d_in[2];
    const int*   atom_to_pair  = (const int*)  d_in[3];
    const float* W_AA = (const float*)d_in[4];
    const float* b_AA = (const float*)d_in[5];
    const float* W_PA = (const float*)d_in[6];
    const float* b_PA = (const float*)d_in[7];
    const float* W_A  = (const float*)d_in[8];
    const float* b_A  = (const float*)d_in[9];
    const float* W_AP = (const float*)d_in[10];
    const float* b_AP = (const float*)d_in[11];
    const float* W_PP = (const float*)d_in[12];
    const float* b_PP = (const float*)d_in[13];
    const float* W_P  = (const float*)d_in[14];
    const float* b_P  = (const float*)d_in[15];

    float* outA = (float*)d_out;                        // [100000, 50]
    float* outP = (float*)d_out + (size_t)N_ATOMS * 50; // [1600000, 50]

    cudaFuncSetAttribute(k1_atoms,    cudaFuncAttributeMaxDynamicSharedMemorySize, (int)sizeof(K1S));
    cudaFuncSetAttribute(k2_pairs,    cudaFuncAttributeMaxDynamicSharedMemorySize, (int)sizeof(K2S));
    cudaFuncSetAttribute(k3_atomsout, cudaFuncAttributeMaxDynamicSharedMemorySize, (int)sizeof(K3S));

    k1_atoms<<<(N_ATOMS + 127) / 128, 512, sizeof(K1S)>>>(atom_features, W_AA, b_AA, W_AP);
    k2_pairs<<<N_PAIRS / 256, 1024, sizeof(K2S)>>>(pair_features, pair_split, atom_to_pair,
                                                   W_PA, b_PA, W_PP, b_PP, W_P, b_P, b_AP, outP);
    k3_atomsout<<<(N_ATOMS + 255) / 256, 512, sizeof(K3S)>>>(W_A, b_A, outA);
}

// round 5
// speedup vs baseline: 1.2821x; 1.2821x over previous
#include <cuda_runtime.h>
#include <cuda_fp16.h>
#include <mma.h>

using namespace nvcuda;

#define N_ATOMS  100000
#define N_PAIRS  1600000
#define N_TILES  (N_PAIRS / 256)     // 6250
#define K2_GRID  296

// ---------------- scratch (device globals; no allocation allowed) ----------
// g_uv interleaved: g_uv[atom*100 + 2k] = u_k, [.. +1] = v_k  (fp16, 20MB)
__device__ __half g_uv [(size_t)N_ATOMS * 100];
__device__ __half g_AA [(size_t)N_ATOMS * 50];
__device__ float  g_PA [(size_t)N_ATOMS * 50];

__device__ __forceinline__ float frelu(float x) { return fmaxf(x, 0.f); }

// ============================================================================
// K1: per-atom GEMM. X = af(128x80pad) @ W(80x160) -> AA | u | v.  Zero g_PA.
// ============================================================================
struct K1S {
    union {
        struct { __half Af[128 * 80]; __half Wt[80 * 160]; };
        float C[128 * 160];
    };
    float bAA[64];
};

__global__ __launch_bounds__(512) void k1_atoms(
    const float* __restrict__ af,
    const float* __restrict__ W_AA, const float* __restrict__ b_AA,
    const float* __restrict__ W_AP)
{
    extern __shared__ char smem_raw[];
    K1S& S = *reinterpret_cast<K1S*>(smem_raw);
    const int tid  = threadIdx.x;
    const int base = blockIdx.x * 128;

    for (int idx = tid; idx < 80 * 160; idx += 512) {
        int d = idx / 160, n = idx - d * 160;
        float w = 0.f;
        if (d < 75) {
            if      (n < 50)  w = W_AA[d * 50 + n];
            else if (n < 100) w = W_AP[d * 50 + (n - 50)];
            else if (n < 150) w = W_AP[(75 + d) * 50 + (n - 100)];
        }
        S.Wt[idx] = __float2half(w);
    }
    for (int idx = tid; idx < 128 * 80; idx += 512) {
        int m = idx / 80, d = idx - m * 80;
        int ga = base + m;
        float v = (ga < N_ATOMS && d < 75) ? af[(size_t)ga * 75 + d] : 0.f;
        S.Af[idx] = __float2half(v);
    }
    if (tid < 50) S.bAA[tid] = b_AA[tid];
    for (int idx = tid; idx < 128 * 50; idx += 512) {
        int ga = base + idx / 50;
        if (ga < N_ATOMS) g_PA[(size_t)ga * 50 + (idx % 50)] = 0.f;
    }
    __syncthreads();

    const int warp = tid >> 5;
    const int mt = warp >> 1;
    const int nb = (warp & 1) * 5;

    wmma::fragment<wmma::accumulator, 16, 16, 16, float> acc[5];
    #pragma unroll
    for (int q = 0; q < 5; q++) wmma::fill_fragment(acc[q], 0.f);
    #pragma unroll
    for (int k = 0; k < 5; k++) {
        wmma::fragment<wmma::matrix_a, 16, 16, 16, __half, wmma::row_major> a;
        wmma::load_matrix_sync(a, S.Af + mt * 16 * 80 + k * 16, 80);
        #pragma unroll
        for (int q = 0; q < 5; q++) {
            wmma::fragment<wmma::matrix_b, 16, 16, 16, __half, wmma::row_major> b;
            wmma::load_matrix_sync(b, S.Wt + k * 16 * 160 + (nb + q) * 16, 160);
            wmma::mma_sync(acc[q], a, b, acc[q]);
        }
    }
    __syncthreads();
    #pragma unroll
    for (int q = 0; q < 5; q++)
        wmma::store_matrix_sync(S.C + mt * 16 * 160 + (nb + q) * 16, acc[q], 160,
                                wmma::mem_row_major);
    __syncthreads();

    for (int idx = tid; idx < 128 * 25; idx += 512) {
        int m = idx / 25, q = idx - m * 25;
        int ga = base + m;
        if (ga >= N_ATOMS) continue;
        float lo = frelu(S.C[m * 160 + 2 * q]     + S.bAA[2 * q]);
        float hi = frelu(S.C[m * 160 + 2 * q + 1] + S.bAA[2 * q + 1]);
        ((__half2*)g_AA)[(size_t)ga * 25 + q] = __floats2half2_rn(lo, hi);
    }
    for (int idx = tid; idx < 128 * 50; idx += 512) {
        int m = idx / 50, n = idx - m * 50;
        int ga = base + m;
        if (ga >= N_ATOMS) continue;
        float u = S.C[m * 160 + 50 + n];
        float v = S.C[m * 160 + 100 + n];
        ((__half2*)g_uv)[(size_t)ga * 50 + n] = __floats2half2_rn(u, v);
    }
}

// ============================================================================
// K2: persistent fused pair kernel. 512 threads, 2 blocks/SM, ~21 tiles/block.
//  Weights staged ONCE per block. Per 256-pair tile:
//   G : s[k]=relu(u_i+v_j+b)+relu(u_j+v_i+b) -> T[:,0:50]
//   A : SIMT (float4 pf): PP -> T[:,50:100], PA -> run-compressed atomics
//   M : T(256x112) @ Wp(112x64, b_P folded via ones-col 100) -> C (union T)
//   E : outP = relu(C)
// ============================================================================
struct K2S {
    union {
        __half T[256 * 112];     // 57344
        float  C[256 * 64];      // 65536
    };
    float  pf [256 * 16];        // 16384 (padded rows, float4-loadable)
    __half Wp [112 * 64];        // 14336
    float  Wpa[14 * 52];         // 2912
    float  Wpp[14 * 52];         // 2912
    float  bAP[64], bPA[64], bPP[64];
    int    ii[256], jj[256], seg[256];
};

__global__ __launch_bounds__(512, 2) void k2_pairs(
    const float* __restrict__ pair_features,
    const int*   __restrict__ pair_split,
    const int*   __restrict__ atom_to_pair,
    const float* __restrict__ W_PA, const float* __restrict__ b_PA,
    const float* __restrict__ W_PP, const float* __restrict__ b_PP,
    const float* __restrict__ W_P,  const float* __restrict__ b_P,
    const float* __restrict__ b_AP,
    float* __restrict__ outP)
{
    extern __shared__ char smem_raw[];
    K2S& S = *reinterpret_cast<K2S*>(smem_raw);
    const int tid = threadIdx.x;

    // ---- stage weights/biases ONCE ----
    for (int idx = tid; idx < 112 * 64; idx += 512) {
        int k = idx >> 6, n = idx & 63;
        float w = 0.f;
        if (n < 50) {
            if      (k < 100)  w = W_P[k * 50 + n];
            else if (k == 100) w = b_P[n];
        }
        S.Wp[idx] = __float2half(w);
    }
    for (int idx = tid; idx < 14 * 52; idx += 512) {
        int d = idx / 52, n = idx - d * 52;
        S.Wpa[idx] = (n < 50) ? W_PA[d * 50 + n] : 0.f;
        S.Wpp[idx] = (n < 50) ? W_PP[d * 50 + n] : 0.f;
    }
    if (tid < 64) {
        S.bAP[tid] = (tid < 50) ? b_AP[tid] : 0.f;
        S.bPA[tid] = (tid < 50) ? b_PA[tid] : 0.f;
        S.bPP[tid] = (tid < 50) ? b_PP[tid] : 0.f;
    }

    for (int tile = blockIdx.x; tile < N_TILES; tile += K2_GRID) {
        const int base = tile * 256;
        __syncthreads();   // previous tile's E reads done before restage

        // ---- per-tile stage ----
        for (int idx = tid; idx < 256 * 16; idx += 512) {
            int p = idx >> 4, d = idx & 15;
            S.pf[idx] = (d < 14) ? pair_features[(size_t)(base + p) * 14 + d] : 0.f;
        }
        if (tid < 256) {
            int2 p2 = ((const int2*)atom_to_pair)[base + tid];
            S.ii[tid] = p2.x;
            S.jj[tid] = p2.y;
            S.seg[tid] = pair_split[base + tid];
        }
        // T cols 100..111: col 100 = 1 (b_P fold), rest 0 (C overwrote last tile)
        for (int idx = tid; idx < 256 * 6; idx += 512) {
            int p = idx / 6, q = idx - p * 6;
            ((__half2*)(S.T + p * 112 + 100))[q] =
                (q == 0) ? __floats2half2_rn(1.f, 0.f) : __floats2half2_rn(0.f, 0.f);
        }
        __syncthreads();

        // ---- G: symmetrized AP -> T[:,0:50] (16 threads/pair, 8 passes) ----
        {
            const int t = tid & 15;
            #pragma unroll
            for (int pass = 0; pass < 8; pass++) {
                const int p = pass * 32 + (tid >> 4);
                const int i = S.ii[p], j = S.jj[p];
                const __half2* ri = (const __half2*)g_uv + (size_t)i * 50;
                const __half2* rj = (const __half2*)g_uv + (size_t)j * 50;
                #pragma unroll
                for (int q = 0; q < 3; q++) {
                    int k = t + q * 16;
                    __half2 a = __ldg(ri + k), b = __ldg(rj + k);
                    float ui = __low2float(a), vi = __high2float(a);
                    float uj = __low2float(b), vj = __high2float(b);
                    float bb = S.bAP[k];
                    S.T[p * 112 + k] =
                        __float2half(frelu(ui + vj + bb) + frelu(uj + vi + bb));
                }
                if (t < 2) {
                    int k = 48 + t;
                    __half2 a = __ldg(ri + k), b = __ldg(rj + k);
                    float ui = __low2float(a), vi = __high2float(a);
                    float uj = __low2float(b), vj = __high2float(b);
                    float bb = S.bAP[k];
                    S.T[p * 112 + k] =
                        __float2half(frelu(ui + vj + bb) + frelu(uj + vi + bb));
                }
            }
        }

        // ---- A: PP -> T[:,50:100], PA -> segmented atomics (float4 pf) ----
        if (tid < 400) {
            const int col = tid % 50, chunk = tid / 50;    // 8 chunks x 32 rows
            float wpa[14], wpp[14];
            #pragma unroll
            for (int d = 0; d < 14; d++) {
                wpa[d] = S.Wpa[d * 52 + col];
                wpp[d] = S.Wpp[d * 52 + col];
            }
            const float bpa = S.bPA[col], bpp = S.bPP[col];
            const int r0 = chunk * 32;
            float acc = 0.f;
            int cur = S.seg[r0];
            for (int r = r0; r < r0 + 32; r++) {
                const float4* pf4 = (const float4*)&S.pf[r * 16];
                float4 q0 = pf4[0], q1 = pf4[1], q2 = pf4[2];
                float2 q3 = *(const float2*)&S.pf[r * 16 + 12];
                float sa = bpa, sp = bpp;
                sa += q0.x * wpa[0];  sp += q0.x * wpp[0];
                sa += q0.y * wpa[1];  sp += q0.y * wpp[1];
                sa += q0.z * wpa[2];  sp += q0.z * wpp[2];
                sa += q0.w * wpa[3];  sp += q0.w * wpp[3];
                sa += q1.x * wpa[4];  sp += q1.x * wpp[4];
                sa += q1.y * wpa[5];  sp += q1.y * wpp[5];
                sa += q1.z * wpa[6];  sp += q1.z * wpp[6];
                sa += q1.w * wpa[7];  sp += q1.w * wpp[7];
                sa += q2.x * wpa[8];  sp += q2.x * wpp[8];
                sa += q2.y * wpa[9];  sp += q2.y * wpp[9];
                sa += q2.z * wpa[10]; sp += q2.z * wpp[10];
                sa += q2.w * wpa[11]; sp += q2.w * wpp[11];
                sa += q3.x * wpa[12]; sp += q3.x * wpp[12];
                sa += q3.y * wpa[13]; sp += q3.y * wpp[13];
                S.T[r * 112 + 50 + col] = __float2half(frelu(sp));
                int sg = S.seg[r];
                if (sg != cur) {
                    atomicAdd(&g_PA[(size_t)cur * 50 + col], acc);
                    acc = 0.f; cur = sg;
                }
                acc += frelu(sa);
            }
            atomicAdd(&g_PA[(size_t)cur * 50 + col], acc);
        }
        __syncthreads();

        // ---- M: T @ Wp -> C (C unions T; barrier between reads and stores) ----
        {
            const int mt = tid >> 5;                 // 16 warps -> 16 m-tiles
            wmma::fragment<wmma::accumulator, 16, 16, 16, float> acc[4];
            #pragma unroll
            for (int q = 0; q < 4; q++) wmma::fill_fragment(acc[q], 0.f);
            #pragma unroll
            for (int k = 0; k < 7; k++) {
                wmma::fragment<wmma::matrix_a, 16, 16, 16, __half, wmma::row_major> a;
                wmma::load_matrix_sync(a, S.T + mt * 16 * 112 + k * 16, 112);
                #pragma unroll
                for (int q = 0; q < 4; q++) {
                    wmma::fragment<wmma::matrix_b, 16, 16, 16, __half, wmma::row_major> b;
                    wmma::load_matrix_sync(b, S.Wp + k * 16 * 64 + q * 16, 64);
                    wmma::mma_sync(acc[q], a, b, acc[q]);
                }
            }
            __syncthreads();           // all T reads done before C overwrite
            #pragma unroll
            for (int q = 0; q < 4; q++)
                wmma::store_matrix_sync(S.C + mt * 16 * 64 + q * 16, acc[q], 64,
                                        wmma::mem_row_major);
        }
        __syncthreads();

        // ---- E: outP = relu(C)  (float2 stores; b_P already folded) ----
        for (int idx = tid; idx < 256 * 25; idx += 512) {
            int p = idx / 25, q = idx - p * 25;
            float2 c = *(const float2*)&S.C[p * 64 + 2 * q];
            c.x = frelu(c.x); c.y = frelu(c.y);
            *(float2*)&outP[(size_t)(base + p) * 50 + 2 * q] = c;
        }
    }
}

// ============================================================================
// K3: atom output GEMM. [AA|PA](256x112pad) @ W_A(112x64pad) -> A.
// ============================================================================
struct K3S {
    union {
        __half X[256 * 112];
        float  C[256 * 64];
    };
    __half W[112 * 64];
    float  bA[64];
};

__global__ __launch_bounds__(512) void k3_atomsout(
    const float* __restrict__ W_A, const float* __restrict__ b_A,
    float* __restrict__ outA)
{
    extern __shared__ char smem_raw[];
    K3S& S = *reinterpret_cast<K3S*>(smem_raw);
    const int tid  = threadIdx.x;
    const int base = blockIdx.x * 256;

    for (int idx = tid; idx < 256 * 112; idx += 512) {
        int m = idx / 112, k = idx - m * 112;
        int ga = base + m;
        __half v = __float2half(0.f);
        if (ga < N_ATOMS) {
            if      (k < 50)  v = g_AA[(size_t)ga * 50 + k];
            else if (k < 100) v = __float2half(g_PA[(size_t)ga * 50 + (k - 50)]);
        }
        S.X[idx] = v;
    }
    for (int idx = tid; idx < 112 * 64; idx += 512) {
        int k = idx / 64, n = idx - k * 64;
        float w = (k < 100 && n < 50) ? W_A[k * 50 + n] : 0.f;
        S.W[idx] = __float2half(w);
    }
    if (tid < 64) S.bA[tid] = (tid < 50) ? b_A[tid] : 0.f;
    __syncthreads();

    {
        const int mt = tid >> 5;
        wmma::fragment<wmma::accumulator, 16, 16, 16, float> acc[4];
        #pragma unroll
        for (int q = 0; q < 4; q++) wmma::fill_fragment(acc[q], 0.f);
        #pragma unroll
        for (int k = 0; k < 7; k++) {
            wmma::fragment<wmma::matrix_a, 16, 16, 16, __half, wmma::row_major> a;
            wmma::load_matrix_sync(a, S.X + mt * 16 * 112 + k * 16, 112);
            #pragma unroll
            for (int q = 0; q < 4; q++) {
                wmma::fragment<wmma::matrix_b, 16, 16, 16, __half, wmma::row_major> b;
                wmma::load_matrix_sync(b, S.W + k * 16 * 64 + q * 16, 64);
                wmma::mma_sync(acc[q], a, b, acc[q]);
            }
        }
        __syncthreads();
        #pragma unroll
        for (int q = 0; q < 4; q++)
            wmma::store_matrix_sync(S.C + mt * 16 * 64 + q * 16, acc[q], 64,
                                    wmma::mem_row_major);
    }
    __syncthreads();

    for (int idx = tid; idx < 256 * 50; idx += 512) {
        int m = idx / 50, n = idx - m * 50;
        int ga = base + m;
        if (ga < N_ATOMS)
            outA[(size_t)ga * 50 + n] = frelu(S.C[m * 64 + n] + S.bA[n]);
    }
}

// ============================================================================
extern "C" void kernel_launch(void* const* d_in, const int* in_sizes, int n_in,
                              void* d_out, int out_size) {
    const float* atom_features = (const float*)d_in[0];
    const float* pair_features = (const float*)d_in[1];
    const int*   pair_split    = (const int*)  d_in[2];
    const int*   atom_to_pair  = (const int*)  d_in[3];
    const float* W_AA = (const float*)d_in[4];
    const float* b_AA = (const float*)d_in[5];
    const float* W_PA = (const float*)d_in[6];
    const float* b_PA = (const float*)d_in[7];
    const float* W_A  = (const float*)d_in[8];
    const float* b_A  = (const float*)d_in[9];
    const float* W_AP = (const float*)d_in[10];
    const float* b_AP = (const float*)d_in[11];
    const float* W_PP = (const float*)d_in[12];
    const float* b_PP = (const float*)d_in[13];
    const float* W_P  = (const float*)d_in[14];
    const float* b_P  = (const float*)d_in[15];

    float* outA = (float*)d_out;                        // [100000, 50]
    float* outP = (float*)d_out + (size_t)N_ATOMS * 50; // [1600000, 50]

    cudaFuncSetAttribute(k1_atoms,    cudaFuncAttributeMaxDynamicSharedMemorySize, (int)sizeof(K1S));
    cudaFuncSetAttribute(k2_pairs,    cudaFuncAttributeMaxDynamicSharedMemorySize, (int)sizeof(K2S));
    cudaFuncSetAttribute(k3_atomsout, cudaFuncAttributeMaxDynamicSharedMemorySize, (int)sizeof(K3S));

    k1_atoms<<<(N_ATOMS + 127) / 128, 512, sizeof(K1S)>>>(atom_features, W_AA, b_AA, W_AP);
    k2_pairs<<<K2_GRID, 512, sizeof(K2S)>>>(pair_features, pair_split, atom_to_pair,
                                            W_PA, b_PA, W_PP, b_PP, W_P, b_P, b_AP, outP);
    k3_atomsout<<<(N_ATOMS + 255) / 256, 512, sizeof(K3S)>>>(W_A, b_A, outA);
}

// round 6
// speedup vs baseline: 2.0717x; 1.6159x over previous
#include <cuda_runtime.h>
#include <cuda_fp16.h>
#include <mma.h>

using namespace nvcuda;

#define N_ATOMS  100000
#define N_PAIRS  1600000
#define N_TILES  (N_PAIRS / 256)     // 6250
#define K2_GRID  296

// conflict-free smem strides
#define TSTR   120   // T stride (halves): 240B/row -> distinct bank phases
#define WSTR   72    // weight stride (halves): 144B/row -> distinct
#define CSTR   68    // C stride (floats): 272B/row -> distinct
#define AFSTR  88    // k1 A stride (halves)
#define WTSTR  168   // k1 W stride (halves)
#define C1STR  164   // k1 C stride (floats)

// ---------------- scratch (device globals; no allocation allowed) ----------
// g_uv interleaved: g_uv[atom*100 + 2k] = u_k, [.. +1] = v_k  (fp16, 20MB)
__device__ __half g_uv [(size_t)N_ATOMS * 100];
__device__ __half g_AA [(size_t)N_ATOMS * 50];
__device__ float  g_PA [(size_t)N_ATOMS * 50];

__device__ __forceinline__ float frelu(float x) { return fmaxf(x, 0.f); }

// ============================================================================
// K1: per-atom GEMM. X = af(128x88pad) @ W(88x168pad) -> AA | u | v. Zero g_PA.
// ============================================================================
struct K1S {
    union {
        struct { __half Af[128 * AFSTR]; __half Wt[80 * WTSTR]; };
        float C[128 * C1STR];
    };
    float bAA[64];
};

__global__ __launch_bounds__(512) void k1_atoms(
    const float* __restrict__ af,
    const float* __restrict__ W_AA, const float* __restrict__ b_AA,
    const float* __restrict__ W_AP)
{
    extern __shared__ char smem_raw[];
    K1S& S = *reinterpret_cast<K1S*>(smem_raw);
    const int tid  = threadIdx.x;
    const int base = blockIdx.x * 128;

    for (int idx = tid; idx < 80 * WTSTR; idx += 512) {
        int d = idx / WTSTR, n = idx - d * WTSTR;
        float w = 0.f;
        if (d < 75) {
            if      (n < 50)  w = W_AA[d * 50 + n];
            else if (n < 100) w = W_AP[d * 50 + (n - 50)];
            else if (n < 150) w = W_AP[(75 + d) * 50 + (n - 100)];
        }
        S.Wt[idx] = __float2half(w);
    }
    for (int idx = tid; idx < 128 * AFSTR; idx += 512) {
        int m = idx / AFSTR, d = idx - m * AFSTR;
        int ga = base + m;
        float v = (ga < N_ATOMS && d < 75) ? af[(size_t)ga * 75 + d] : 0.f;
        S.Af[idx] = __float2half(v);
    }
    if (tid < 50) S.bAA[tid] = b_AA[tid];
    for (int idx = tid; idx < 128 * 50; idx += 512) {
        int ga = base + idx / 50;
        if (ga < N_ATOMS) g_PA[(size_t)ga * 50 + (idx % 50)] = 0.f;
    }
    __syncthreads();

    const int warp = tid >> 5;
    const int mt = warp >> 1;
    const int nb = (warp & 1) * 5;

    wmma::fragment<wmma::accumulator, 16, 16, 16, float> acc[5];
    #pragma unroll
    for (int q = 0; q < 5; q++) wmma::fill_fragment(acc[q], 0.f);
    #pragma unroll
    for (int k = 0; k < 5; k++) {
        wmma::fragment<wmma::matrix_a, 16, 16, 16, __half, wmma::row_major> a;
        wmma::load_matrix_sync(a, S.Af + mt * 16 * AFSTR + k * 16, AFSTR);
        #pragma unroll
        for (int q = 0; q < 5; q++) {
            wmma::fragment<wmma::matrix_b, 16, 16, 16, __half, wmma::row_major> b;
            wmma::load_matrix_sync(b, S.Wt + k * 16 * WTSTR + (nb + q) * 16, WTSTR);
            wmma::mma_sync(acc[q], a, b, acc[q]);
        }
    }
    __syncthreads();
    #pragma unroll
    for (int q = 0; q < 5; q++)
        wmma::store_matrix_sync(S.C + mt * 16 * C1STR + (nb + q) * 16, acc[q], C1STR,
                                wmma::mem_row_major);
    __syncthreads();

    for (int idx = tid; idx < 128 * 25; idx += 512) {
        int m = idx / 25, q = idx - m * 25;
        int ga = base + m;
        if (ga >= N_ATOMS) continue;
        float lo = frelu(S.C[m * C1STR + 2 * q]     + S.bAA[2 * q]);
        float hi = frelu(S.C[m * C1STR + 2 * q + 1] + S.bAA[2 * q + 1]);
        ((__half2*)g_AA)[(size_t)ga * 25 + q] = __floats2half2_rn(lo, hi);
    }
    for (int idx = tid; idx < 128 * 50; idx += 512) {
        int m = idx / 50, n = idx - m * 50;
        int ga = base + m;
        if (ga >= N_ATOMS) continue;
        float u = S.C[m * C1STR + 50 + n];
        float v = S.C[m * C1STR + 100 + n];
        ((__half2*)g_uv)[(size_t)ga * 50 + n] = __floats2half2_rn(u, v);
    }
}

// ============================================================================
// K2: persistent fused pair kernel. 512 threads, 2 blocks/SM, ~21 tiles/block.
// ============================================================================
struct K2S {
    union {
        __half T[256 * TSTR];        // 61440
        float  C[256 * CSTR];        // 69632
    };
    float  pf [256 * 16];            // 16384
    __half Wp [112 * WSTR];          // 16128
    float  Wpa[14 * 52];
    float  Wpp[14 * 52];
    float  bAP[64], bPA[64], bPP[64];
    int    ii[256], jj[256], seg[256];
};

__global__ __launch_bounds__(512, 2) void k2_pairs(
    const float* __restrict__ pair_features,
    const int*   __restrict__ pair_split,
    const int*   __restrict__ atom_to_pair,
    const float* __restrict__ W_PA, const float* __restrict__ b_PA,
    const float* __restrict__ W_PP, const float* __restrict__ b_PP,
    const float* __restrict__ W_P,  const float* __restrict__ b_P,
    const float* __restrict__ b_AP,
    float* __restrict__ outP)
{
    extern __shared__ char smem_raw[];
    K2S& S = *reinterpret_cast<K2S*>(smem_raw);
    const int tid = threadIdx.x;

    // ---- stage weights/biases ONCE ----
    for (int idx = tid; idx < 112 * WSTR; idx += 512) {
        int k = idx / WSTR, n = idx - k * WSTR;
        float w = 0.f;
        if (n < 50) {
            if      (k < 100)  w = W_P[k * 50 + n];
            else if (k == 100) w = b_P[n];
        }
        S.Wp[idx] = __float2half(w);
    }
    for (int idx = tid; idx < 14 * 52; idx += 512) {
        int d = idx / 52, n = idx - d * 52;
        S.Wpa[idx] = (n < 50) ? W_PA[d * 50 + n] : 0.f;
        S.Wpp[idx] = (n < 50) ? W_PP[d * 50 + n] : 0.f;
    }
    if (tid < 64) {
        S.bAP[tid] = (tid < 50) ? b_AP[tid] : 0.f;
        S.bPA[tid] = (tid < 50) ? b_PA[tid] : 0.f;
        S.bPP[tid] = (tid < 50) ? b_PP[tid] : 0.f;
    }

    for (int tile = blockIdx.x; tile < N_TILES; tile += K2_GRID) {
        const int base = tile * 256;
        __syncthreads();   // previous tile's E reads done before restage

        // ---- per-tile stage ----
        for (int idx = tid; idx < 256 * 16; idx += 512) {
            int p = idx >> 4, d = idx & 15;
            S.pf[idx] = (d < 14) ? pair_features[(size_t)(base + p) * 14 + d] : 0.f;
        }
        if (tid < 256) {
            int2 p2 = ((const int2*)atom_to_pair)[base + tid];
            S.ii[tid] = p2.x;
            S.jj[tid] = p2.y;
            S.seg[tid] = pair_split[base + tid];
        }
        // T cols 100..111: col 100 = 1 (b_P fold), 101..111 = 0
        for (int idx = tid; idx < 256 * 6; idx += 512) {
            int p = idx / 6, q = idx - p * 6;
            ((__half2*)(S.T + p * TSTR + 100))[q] =
                (q == 0) ? __floats2half2_rn(1.f, 0.f) : __floats2half2_rn(0.f, 0.f);
        }
        __syncthreads();

        // ---- G: symmetrized AP -> T[:,0:50]  (16 thr/pair, float2 gathers) ----
        {
            const int t = tid & 15;
            #pragma unroll
            for (int pass = 0; pass < 8; pass++) {
                const int p = pass * 32 + (tid >> 4);
                const int i = S.ii[p], j = S.jj[p];
                const float2* ri = (const float2*)(g_uv + (size_t)i * 100);
                const float2* rj = (const float2*)(g_uv + (size_t)j * 100);
                // q = t : covers k = 2t, 2t+1
                {
                    const int q = t;
                    float2 fa = __ldg(ri + q), fb = __ldg(rj + q);
                    __half2 a0 = *(__half2*)&fa.x, a1 = *(__half2*)&fa.y;
                    __half2 b0 = *(__half2*)&fb.x, b1 = *(__half2*)&fb.y;
                    float2 bb = *(const float2*)&S.bAP[2 * q];
                    float s0 = frelu(__low2float(a0) + __high2float(b0) + bb.x)
                             + frelu(__low2float(b0) + __high2float(a0) + bb.x);
                    float s1 = frelu(__low2float(a1) + __high2float(b1) + bb.y)
                             + frelu(__low2float(b1) + __high2float(a1) + bb.y);
                    ((__half2*)(S.T + p * TSTR))[q] = __floats2half2_rn(s0, s1);
                }
                if (t < 9) {
                    const int q = t + 16;
                    float2 fa = __ldg(ri + q), fb = __ldg(rj + q);
                    __half2 a0 = *(__half2*)&fa.x, a1 = *(__half2*)&fa.y;
                    __half2 b0 = *(__half2*)&fb.x, b1 = *(__half2*)&fb.y;
                    float2 bb = *(const float2*)&S.bAP[2 * q];
                    float s0 = frelu(__low2float(a0) + __high2float(b0) + bb.x)
                             + frelu(__low2float(b0) + __high2float(a0) + bb.x);
                    float s1 = frelu(__low2float(a1) + __high2float(b1) + bb.y)
                             + frelu(__low2float(b1) + __high2float(a1) + bb.y);
                    ((__half2*)(S.T + p * TSTR))[q] = __floats2half2_rn(s0, s1);
                }
            }
        }

        // ---- A: PP -> T[:,50:100], PA -> segmented atomics (float4 pf) ----
        if (tid < 400) {
            const int col = tid % 50, chunk = tid / 50;    // 8 chunks x 32 rows
            float wpa[14], wpp[14];
            #pragma unroll
            for (int d = 0; d < 14; d++) {
                wpa[d] = S.Wpa[d * 52 + col];
                wpp[d] = S.Wpp[d * 52 + col];
            }
            const float bpa = S.bPA[col], bpp = S.bPP[col];
            const int r0 = chunk * 32;
            float acc = 0.f;
            int cur = S.seg[r0];
            for (int r = r0; r < r0 + 32; r++) {
                const float4* pf4 = (const float4*)&S.pf[r * 16];
                float4 q0 = pf4[0], q1 = pf4[1], q2 = pf4[2];
                float2 q3 = *(const float2*)&S.pf[r * 16 + 12];
                float sa = bpa, sp = bpp;
                sa += q0.x * wpa[0];  sp += q0.x * wpp[0];
                sa += q0.y * wpa[1];  sp += q0.y * wpp[1];
                sa += q0.z * wpa[2];  sp += q0.z * wpp[2];
                sa += q0.w * wpa[3];  sp += q0.w * wpp[3];
                sa += q1.x * wpa[4];  sp += q1.x * wpp[4];
                sa += q1.y * wpa[5];  sp += q1.y * wpp[5];
                sa += q1.z * wpa[6];  sp += q1.z * wpp[6];
                sa += q1.w * wpa[7];  sp += q1.w * wpp[7];
                sa += q2.x * wpa[8];  sp += q2.x * wpp[8];
                sa += q2.y * wpa[9];  sp += q2.y * wpp[9];
                sa += q2.z * wpa[10]; sp += q2.z * wpp[10];
                sa += q2.w * wpa[11]; sp += q2.w * wpp[11];
                sa += q3.x * wpa[12]; sp += q3.x * wpp[12];
                sa += q3.y * wpa[13]; sp += q3.y * wpp[13];
                S.T[r * TSTR + 50 + col] = __float2half(frelu(sp));
                int sg = S.seg[r];
                if (sg != cur) {
                    atomicAdd(&g_PA[(size_t)cur * 50 + col], acc);
                    acc = 0.f; cur = sg;
                }
                acc += frelu(sa);
            }
            atomicAdd(&g_PA[(size_t)cur * 50 + col], acc);
        }
        __syncthreads();

        // ---- M: T @ Wp -> C ----
        {
            const int mt = tid >> 5;                 // 16 warps -> 16 m-tiles
            wmma::fragment<wmma::accumulator, 16, 16, 16, float> acc[4];
            #pragma unroll
            for (int q = 0; q < 4; q++) wmma::fill_fragment(acc[q], 0.f);
            #pragma unroll
            for (int k = 0; k < 7; k++) {
                wmma::fragment<wmma::matrix_a, 16, 16, 16, __half, wmma::row_major> a;
                wmma::load_matrix_sync(a, S.T + mt * 16 * TSTR + k * 16, TSTR);
                #pragma unroll
                for (int q = 0; q < 4; q++) {
                    wmma::fragment<wmma::matrix_b, 16, 16, 16, __half, wmma::row_major> b;
                    wmma::load_matrix_sync(b, S.Wp + k * 16 * WSTR + q * 16, WSTR);
                    wmma::mma_sync(acc[q], a, b, acc[q]);
                }
            }
            __syncthreads();           // all T reads done before C overwrite
            #pragma unroll
            for (int q = 0; q < 4; q++)
                wmma::store_matrix_sync(S.C + mt * 16 * CSTR + q * 16, acc[q], CSTR,
                                        wmma::mem_row_major);
        }
        __syncthreads();

        // ---- E: outP = relu(C) ----
        for (int idx = tid; idx < 256 * 25; idx += 512) {
            int p = idx / 25, q = idx - p * 25;
            float2 c = *(const float2*)&S.C[p * CSTR + 2 * q];
            c.x = frelu(c.x); c.y = frelu(c.y);
            *(float2*)&outP[(size_t)(base + p) * 50 + 2 * q] = c;
        }
    }
}

// ============================================================================
// K3: atom output GEMM. [AA|PA](256x120pad) @ W_A(120x72pad) -> A.
// ============================================================================
struct K3S {
    union {
        __half X[256 * TSTR];
        float  C[256 * CSTR];
    };
    __half W[112 * WSTR];
    float  bA[64];
};

__global__ __launch_bounds__(512) void k3_atomsout(
    const float* __restrict__ W_A, const float* __restrict__ b_A,
    float* __restrict__ outA)
{
    extern __shared__ char smem_raw[];
    K3S& S = *reinterpret_cast<K3S*>(smem_raw);
    const int tid  = threadIdx.x;
    const int base = blockIdx.x * 256;

    for (int idx = tid; idx < 256 * TSTR; idx += 512) {
        int m = idx / TSTR, k = idx - m * TSTR;
        int ga = base + m;
        __half v = __float2half(0.f);
        if (ga < N_ATOMS) {
            if      (k < 50)  v = g_AA[(size_t)ga * 50 + k];
            else if (k < 100) v = __float2half(g_PA[(size_t)ga * 50 + (k - 50)]);
        }
        S.X[idx] = v;
    }
    for (int idx = tid; idx < 112 * WSTR; idx += 512) {
        int k = idx / WSTR, n = idx - k * WSTR;
        float w = (k < 100 && n < 50) ? W_A[k * 50 + n] : 0.f;
        S.W[idx] = __float2half(w);
    }
    if (tid < 64) S.bA[tid] = (tid < 50) ? b_A[tid] : 0.f;
    __syncthreads();

    {
        const int mt = tid >> 5;
        wmma::fragment<wmma::accumulator, 16, 16, 16, float> acc[4];
        #pragma unroll
        for (int q = 0; q < 4; q++) wmma::fill_fragment(acc[q], 0.f);
        #pragma unroll
        for (int k = 0; k < 7; k++) {
            wmma::fragment<wmma::matrix_a, 16, 16, 16, __half, wmma::row_major> a;
            wmma::load_matrix_sync(a, S.X + mt * 16 * TSTR + k * 16, TSTR);
            #pragma unroll
            for (int q = 0; q < 4; q++) {
                wmma::fragment<wmma::matrix_b, 16, 16, 16, __half, wmma::row_major> b;
                wmma::load_matrix_sync(b, S.W + k * 16 * WSTR + q * 16, WSTR);
                wmma::mma_sync(acc[q], a, b, acc[q]);
            }
        }
        __syncthreads();
        #pragma unroll
        for (int q = 0; q < 4; q++)
            wmma::store_matrix_sync(S.C + mt * 16 * CSTR + q * 16, acc[q], CSTR,
                                    wmma::mem_row_major);
    }
    __syncthreads();

    for (int idx = tid; idx < 256 * 50; idx += 512) {
        int m = idx / 50, n = idx - m * 50;
        int ga = base + m;
        if (ga < N_ATOMS)
            outA[(size_t)ga * 50 + n] = frelu(S.C[m * CSTR + n] + S.bA[n]);
    }
}

// ============================================================================
extern "C" void kernel_launch(void* const* d_in, const int* in_sizes, int n_in,
                              void* d_out, int out_size) {
    const float* atom_features = (const float*)d_in[0];
    const float* pair_features = (const float*)d_in[1];
    const int*   pair_split    = (const int*)  d_in[2];
    const int*   atom_to_pair  = (const int*)  d_in[3];
    const float* W_AA = (const float*)d_in[4];
    const float* b_AA = (const float*)d_in[5];
    const float* W_PA = (const float*)d_in[6];
    const float* b_PA = (const float*)d_in[7];
    const float* W_A  = (const float*)d_in[8];
    const float* b_A  = (const float*)d_in[9];
    const float* W_AP = (const float*)d_in[10];
    const float* b_AP = (const float*)d_in[11];
    const float* W_PP = (const float*)d_in[12];
    const float* b_PP = (const float*)d_in[13];
    const float* W_P  = (const float*)d_in[14];
    const float* b_P  = (const float*)d_in[15];

    float* outA = (float*)d_out;                        // [100000, 50]
    float* outP = (float*)d_out + (size_t)N_ATOMS * 50; // [1600000, 50]

    cudaFuncSetAttribute(k1_atoms,    cudaFuncAttributeMaxDynamicSharedMemorySize, (int)sizeof(K1S));
    cudaFuncSetAttribute(k2_pairs,    cudaFuncAttributeMaxDynamicSharedMemorySize, (int)sizeof(K2S));
    cudaFuncSetAttribute(k3_atomsout, cudaFuncAttributeMaxDynamicSharedMemorySize, (int)sizeof(K3S));

    k1_atoms<<<(N_ATOMS + 127) / 128, 512, sizeof(K1S)>>>(atom_features, W_AA, b_AA, W_AP);
    k2_pairs<<<K2_GRID, 512, sizeof(K2S)>>>(pair_features, pair_split, atom_to_pair,
                                            W_PA, b_PA, W_PP, b_PP, W_P, b_P, b_AP, outP);
    k3_atomsout<<<(N_ATOMS + 255) / 256, 512, sizeof(K3S)>>>(W_A, b_A, outA);
}

// round 7
// speedup vs baseline: 2.4113x; 1.1639x over previous
#include <cuda_runtime.h>
#include <cuda_fp16.h>
#include <mma.h>

using namespace nvcuda;

#define N_ATOMS  100000
#define N_PAIRS  1600000
#define N_TILES  (N_PAIRS / 256)     // 6250
#define K2_GRID  296

// conflict-free smem strides (half strides mult of 8, float strides mult of 4)
#define TSTR   120   // T stride (halves): 240B/row
#define DSTR   72    // D stride (halves): 144B/row
#define WSTR   72    // Wp stride (halves)
#define WCSTR  136   // Wc stride (halves): 272B/row
#define PFSTR  16    // pfh stride (halves)
#define CSTR   68    // C stride (floats): 272B/row
#define AFSTR  88    // k1 A stride (halves)
#define WTSTR  168   // k1 W stride (halves)
#define C1STR  164   // k1 C stride (floats)

// ---------------- scratch (device globals; no allocation allowed) ----------
__device__ __half g_uv [(size_t)N_ATOMS * 100];
__device__ __half g_AA [(size_t)N_ATOMS * 50];
__device__ float  g_PA [(size_t)N_ATOMS * 50];

__device__ __forceinline__ float frelu(float x) { return fmaxf(x, 0.f); }

// ============================================================================
// K1: per-atom GEMM. X = af(128x88pad) @ W(88x168pad) -> AA | u | v. Zero g_PA.
// ============================================================================
struct K1S {
    union {
        struct { __half Af[128 * AFSTR]; __half Wt[80 * WTSTR]; };
        float C[128 * C1STR];
    };
    float bAA[64];
};

__global__ __launch_bounds__(512) void k1_atoms(
    const float* __restrict__ af,
    const float* __restrict__ W_AA, const float* __restrict__ b_AA,
    const float* __restrict__ W_AP)
{
    extern __shared__ char smem_raw[];
    K1S& S = *reinterpret_cast<K1S*>(smem_raw);
    const int tid  = threadIdx.x;
    const int base = blockIdx.x * 128;

    for (int idx = tid; idx < 80 * WTSTR; idx += 512) {
        int d = idx / WTSTR, n = idx - d * WTSTR;
        float w = 0.f;
        if (d < 75) {
            if      (n < 50)  w = W_AA[d * 50 + n];
            else if (n < 100) w = W_AP[d * 50 + (n - 50)];
            else if (n < 150) w = W_AP[(75 + d) * 50 + (n - 100)];
        }
        S.Wt[idx] = __float2half(w);
    }
    for (int idx = tid; idx < 128 * AFSTR; idx += 512) {
        int m = idx / AFSTR, d = idx - m * AFSTR;
        int ga = base + m;
        float v = (ga < N_ATOMS && d < 75) ? af[(size_t)ga * 75 + d] : 0.f;
        S.Af[idx] = __float2half(v);
    }
    if (tid < 50) S.bAA[tid] = b_AA[tid];
    for (int idx = tid; idx < 128 * 50; idx += 512) {
        int ga = base + idx / 50;
        if (ga < N_ATOMS) g_PA[(size_t)ga * 50 + (idx % 50)] = 0.f;
    }
    __syncthreads();

    const int warp = tid >> 5;
    const int mt = warp >> 1;
    const int nb = (warp & 1) * 5;

    wmma::fragment<wmma::accumulator, 16, 16, 16, float> acc[5];
    #pragma unroll
    for (int q = 0; q < 5; q++) wmma::fill_fragment(acc[q], 0.f);
    #pragma unroll
    for (int k = 0; k < 5; k++) {
        wmma::fragment<wmma::matrix_a, 16, 16, 16, __half, wmma::row_major> a;
        wmma::load_matrix_sync(a, S.Af + mt * 16 * AFSTR + k * 16, AFSTR);
        #pragma unroll
        for (int q = 0; q < 5; q++) {
            wmma::fragment<wmma::matrix_b, 16, 16, 16, __half, wmma::row_major> b;
            wmma::load_matrix_sync(b, S.Wt + k * 16 * WTSTR + (nb + q) * 16, WTSTR);
            wmma::mma_sync(acc[q], a, b, acc[q]);
        }
    }
    __syncthreads();
    #pragma unroll
    for (int q = 0; q < 5; q++)
        wmma::store_matrix_sync(S.C + mt * 16 * C1STR + (nb + q) * 16, acc[q], C1STR,
                                wmma::mem_row_major);
    __syncthreads();

    for (int idx = tid; idx < 128 * 25; idx += 512) {
        int m = idx / 25, q = idx - m * 25;
        int ga = base + m;
        if (ga >= N_ATOMS) continue;
        float lo = frelu(S.C[m * C1STR + 2 * q]     + S.bAA[2 * q]);
        float hi = frelu(S.C[m * C1STR + 2 * q + 1] + S.bAA[2 * q + 1]);
        ((__half2*)g_AA)[(size_t)ga * 25 + q] = __floats2half2_rn(lo, hi);
    }
    for (int idx = tid; idx < 128 * 50; idx += 512) {
        int m = idx / 50, n = idx - m * 50;
        int ga = base + m;
        if (ga >= N_ATOMS) continue;
        float u = S.C[m * C1STR + 50 + n];
        float v = S.C[m * C1STR + 100 + n];
        ((__half2*)g_uv)[(size_t)ga * 50 + n] = __floats2half2_rn(u, v);
    }
}

// ============================================================================
// K2: persistent fused pair kernel. 512 threads, 2 blocks/SM.
//  T layout (cols): 0..49 = s (G phase), 50..51 = 0, 52..101 = PP, 102 = 1
//  (b_P fold), 103..115 = 0.  Wp rows remapped to match.
//  W1a: pfh @ Wc[PP] -> T[:,52:102) (fp16 acc, relu on fragment)
//  W1b: pfh @ Wc[PA] -> D (two 128-row halves), atomics read D.
// ============================================================================
struct K2S {
    union {
        struct { __half T[256 * TSTR]; __half D[128 * DSTR]; };  // 61440+18432
        float C[256 * CSTR];                                     // 69632
    };
    __half pfh[256 * PFSTR];     // 8192
    __half Wc [16 * WCSTR];      // 4352: cols 0..49 PA, 64..113 PP; row 14 = bias
    __half Wp [112 * WSTR];      // 16128
    float  bAP[64];
    int    ii[256], jj[256], seg[256];
};

__global__ __launch_bounds__(512, 2) void k2_pairs(
    const float* __restrict__ pair_features,
    const int*   __restrict__ pair_split,
    const int*   __restrict__ atom_to_pair,
    const float* __restrict__ W_PA, const float* __restrict__ b_PA,
    const float* __restrict__ W_PP, const float* __restrict__ b_PP,
    const float* __restrict__ W_P,  const float* __restrict__ b_P,
    const float* __restrict__ b_AP,
    float* __restrict__ outP)
{
    extern __shared__ char smem_raw[];
    K2S& S = *reinterpret_cast<K2S*>(smem_raw);
    const int tid  = threadIdx.x;
    const int warp = tid >> 5;
    const __half h0 = __float2half(0.f);

    // ---- stage weights/biases ONCE ----
    for (int idx = tid; idx < 112 * WSTR; idx += 512) {
        int k = idx / WSTR, n = idx - k * WSTR;
        float w = 0.f;
        if (n < 50) {
            if      (k < 50)              w = W_P[k * 50 + n];        // s part
            else if (k >= 52 && k < 102)  w = W_P[(k - 2) * 50 + n];  // PP part
            else if (k == 102)            w = b_P[n];
        }
        S.Wp[idx] = __float2half(w);
    }
    for (int idx = tid; idx < 16 * WCSTR; idx += 512) {
        int d = idx / WCSTR, n = idx - d * WCSTR;
        float w = 0.f;
        if (d < 14) {
            if      (n < 50)             w = W_PA[d * 50 + n];
            else if (n >= 64 && n < 114) w = W_PP[d * 50 + (n - 64)];
        } else if (d == 14) {
            if      (n < 50)             w = b_PA[n];
            else if (n >= 64 && n < 114) w = b_PP[n - 64];
        }
        S.Wc[idx] = __float2half(w);
    }
    if (tid < 64) S.bAP[tid] = (tid < 50) ? b_AP[tid] : 0.f;
    // zero T once (cols 50,51 and tails stay 0 forever)
    for (int idx = tid; idx < 256 * TSTR / 2; idx += 512)
        ((__half2*)S.T)[idx] = __floats2half2_rn(0.f, 0.f);

    for (int tile = blockIdx.x; tile < N_TILES; tile += K2_GRID) {
        const int base = tile * 256;
        __syncthreads();   // previous tile's epilogue reads done

        // ---- stage pfh (ones col 14) + indices ----
        for (int idx = tid; idx < 256 * 16; idx += 512) {
            int p = idx >> 4, d = idx & 15;
            float v = (d < 14) ? pair_features[(size_t)(base + p) * 14 + d]
                               : (d == 14 ? 1.f : 0.f);
            S.pfh[idx] = __float2half(v);
        }
        if (tid < 256) {
            int2 p2 = ((const int2*)atom_to_pair)[base + tid];
            S.ii[tid] = p2.x;
            S.jj[tid] = p2.y;
            S.seg[tid] = pair_split[base + tid];
        }
        __syncthreads();

        // ---- W1a: PP -> T[:,52..] (all 256 rows), W1b h=0: PA -> D, G ----
        {
            // PP: warp w -> m-tile w, 4 n-tiles
            wmma::fragment<wmma::matrix_a, 16, 16, 16, __half, wmma::row_major> a;
            wmma::load_matrix_sync(a, S.pfh + warp * 16 * PFSTR, PFSTR);
            #pragma unroll
            for (int q = 0; q < 4; q++) {
                wmma::fragment<wmma::accumulator, 16, 16, 16, __half> c;
                wmma::fill_fragment(c, h0);
                wmma::fragment<wmma::matrix_b, 16, 16, 16, __half, wmma::row_major> b;
                wmma::load_matrix_sync(b, S.Wc + 64 + 16 * q, WCSTR);
                wmma::mma_sync(c, a, b, c);
                #pragma unroll
                for (int e = 0; e < c.num_elements; e++) c.x[e] = __hmax(c.x[e], h0);
                wmma::store_matrix_sync(S.T + warp * 16 * TSTR + 52 + 16 * q, c, TSTR,
                                        wmma::mem_row_major);
            }
            // PA h=0: warp w -> m-tile w>>1 (rows 0..127), n-tiles (w&1)*2 +{0,1}
            const int mt = warp >> 1, nq = (warp & 1) * 2;
            wmma::fragment<wmma::matrix_a, 16, 16, 16, __half, wmma::row_major> a2;
            wmma::load_matrix_sync(a2, S.pfh + mt * 16 * PFSTR, PFSTR);
            #pragma unroll
            for (int q = 0; q < 2; q++) {
                wmma::fragment<wmma::accumulator, 16, 16, 16, __half> c;
                wmma::fill_fragment(c, h0);
                wmma::fragment<wmma::matrix_b, 16, 16, 16, __half, wmma::row_major> b;
                wmma::load_matrix_sync(b, S.Wc + 16 * (nq + q), WCSTR);
                wmma::mma_sync(c, a2, b, c);
                #pragma unroll
                for (int e = 0; e < c.num_elements; e++) c.x[e] = __hmax(c.x[e], h0);
                wmma::store_matrix_sync(S.D + mt * 16 * DSTR + 16 * (nq + q), c, DSTR,
                                        wmma::mem_row_major);
            }
        }
        // G: symmetrized AP -> T[:,0:50] (16 thr/pair, float2 gathers)
        {
            const int t = tid & 15;
            #pragma unroll
            for (int pass = 0; pass < 8; pass++) {
                const int p = pass * 32 + (tid >> 4);
                const int i = S.ii[p], j = S.jj[p];
                const float2* ri = (const float2*)(g_uv + (size_t)i * 100);
                const float2* rj = (const float2*)(g_uv + (size_t)j * 100);
                {
                    const int q = t;
                    float2 fa = __ldg(ri + q), fb = __ldg(rj + q);
                    __half2 a0 = *(__half2*)&fa.x, a1 = *(__half2*)&fa.y;
                    __half2 b0 = *(__half2*)&fb.x, b1 = *(__half2*)&fb.y;
                    float2 bb = *(const float2*)&S.bAP[2 * q];
                    float s0 = frelu(__low2float(a0) + __high2float(b0) + bb.x)
                             + frelu(__low2float(b0) + __high2float(a0) + bb.x);
                    float s1 = frelu(__low2float(a1) + __high2float(b1) + bb.y)
                             + frelu(__low2float(b1) + __high2float(a1) + bb.y);
                    ((__half2*)(S.T + p * TSTR))[q] = __floats2half2_rn(s0, s1);
                }
                if (t < 9) {
                    const int q = t + 16;
                    float2 fa = __ldg(ri + q), fb = __ldg(rj + q);
                    __half2 a0 = *(__half2*)&fa.x, a1 = *(__half2*)&fa.y;
                    __half2 b0 = *(__half2*)&fb.x, b1 = *(__half2*)&fb.y;
                    float2 bb = *(const float2*)&S.bAP[2 * q];
                    float s0 = frelu(__low2float(a0) + __high2float(b0) + bb.x)
                             + frelu(__low2float(b0) + __high2float(a0) + bb.x);
                    float s1 = frelu(__low2float(a1) + __high2float(b1) + bb.y)
                             + frelu(__low2float(b1) + __high2float(a1) + bb.y);
                    ((__half2*)(S.T + p * TSTR))[q] = __floats2half2_rn(s0, s1);
                }
            }
        }
        __syncthreads();

        // ---- atomics h=0: rows 0..127, run-compressed ----
        {
            const int col = tid & 63, chunk = tid >> 6;    // 8 chunks x 16 rows
            if (col < 50) {
                const int r0 = chunk * 16;
                float acc = 0.f;
                int cur = S.seg[r0];
                #pragma unroll 4
                for (int r = r0; r < r0 + 16; r++) {
                    float v = __half2float(S.D[r * DSTR + col]);
                    int sg = S.seg[r];
                    if (sg != cur) {
                        atomicAdd(&g_PA[(size_t)cur * 50 + col], acc);
                        acc = 0.f; cur = sg;
                    }
                    acc += v;
                }
                atomicAdd(&g_PA[(size_t)cur * 50 + col], acc);
            }
        }
        __syncthreads();

        // ---- W1b h=1: PA rows 128..255 -> D ----
        {
            const int mt = warp >> 1, nq = (warp & 1) * 2;
            wmma::fragment<wmma::matrix_a, 16, 16, 16, __half, wmma::row_major> a2;
            wmma::load_matrix_sync(a2, S.pfh + (128 + mt * 16) * PFSTR, PFSTR);
            #pragma unroll
            for (int q = 0; q < 2; q++) {
                wmma::fragment<wmma::accumulator, 16, 16, 16, __half> c;
                wmma::fill_fragment(c, h0);
                wmma::fragment<wmma::matrix_b, 16, 16, 16, __half, wmma::row_major> b;
                wmma::load_matrix_sync(b, S.Wc + 16 * (nq + q), WCSTR);
                wmma::mma_sync(c, a2, b, c);
                #pragma unroll
                for (int e = 0; e < c.num_elements; e++) c.x[e] = __hmax(c.x[e], h0);
                wmma::store_matrix_sync(S.D + mt * 16 * DSTR + 16 * (nq + q), c, DSTR,
                                        wmma::mem_row_major);
            }
        }
        __syncthreads();

        // ---- atomics h=1: rows 128..255 ; restore ones col 102 ----
        {
            const int col = tid & 63, chunk = tid >> 6;
            if (col < 50) {
                const int r0 = chunk * 16;
                float acc = 0.f;
                int cur = S.seg[128 + r0];
                #pragma unroll 4
                for (int r = r0; r < r0 + 16; r++) {
                    float v = __half2float(S.D[r * DSTR + col]);
                    int sg = S.seg[128 + r];
                    if (sg != cur) {
                        atomicAdd(&g_PA[(size_t)cur * 50 + col], acc);
                        acc = 0.f; cur = sg;
                    }
                    acc += v;
                }
                atomicAdd(&g_PA[(size_t)cur * 50 + col], acc);
            }
        }
        if (tid < 256) S.T[tid * TSTR + 102] = __float2half(1.f);
        __syncthreads();

        // ---- M: T @ Wp -> C (C overlays T+D; barrier between reads/stores) ----
        {
            wmma::fragment<wmma::accumulator, 16, 16, 16, float> acc[4];
            #pragma unroll
            for (int q = 0; q < 4; q++) wmma::fill_fragment(acc[q], 0.f);
            #pragma unroll
            for (int k = 0; k < 7; k++) {
                wmma::fragment<wmma::matrix_a, 16, 16, 16, __half, wmma::row_major> a;
                wmma::load_matrix_sync(a, S.T + warp * 16 * TSTR + k * 16, TSTR);
                #pragma unroll
                for (int q = 0; q < 4; q++) {
                    wmma::fragment<wmma::matrix_b, 16, 16, 16, __half, wmma::row_major> b;
                    wmma::load_matrix_sync(b, S.Wp + k * 16 * WSTR + q * 16, WSTR);
                    wmma::mma_sync(acc[q], a, b, acc[q]);
                }
            }
            __syncthreads();           // all T reads done before C overwrite
            #pragma unroll
            for (int q = 0; q < 4; q++)
                wmma::store_matrix_sync(S.C + warp * 16 * CSTR + q * 16, acc[q], CSTR,
                                        wmma::mem_row_major);
        }
        __syncthreads();

        // ---- E: outP = relu(C) ; then T needs re-zeroing of clobbered cols ----
        for (int idx = tid; idx < 256 * 25; idx += 512) {
            int p = idx / 25, q = idx - p * 25;
            float2 c = *(const float2*)&S.C[p * CSTR + 2 * q];
            c.x = frelu(c.x); c.y = frelu(c.y);
            *(float2*)&outP[(size_t)(base + p) * 50 + 2 * q] = c;
        }
        __syncthreads();
        // C overwrote T region: re-zero T cols 50,51 and 103..119 pattern is
        // restored implicitly: G rewrites 0..49, W1a rewrites 52..115 (103..115
        // get relu(0)=0), col 102 reset each tile. Only cols 50,51 and 116..119
        // must be re-zeroed here.
        if (tid < 256) {
            ((__half2*)(S.T + tid * TSTR + 50))[0] = __floats2half2_rn(0.f, 0.f);
            ((__half2*)(S.T + tid * TSTR + 116))[0] = __floats2half2_rn(0.f, 0.f);
            ((__half2*)(S.T + tid * TSTR + 118))[0] = __floats2half2_rn(0.f, 0.f);
        }
    }
}

// ============================================================================
// K3: atom output GEMM. [AA|PA](256x120pad) @ W_A(120x72pad) -> A.
// ============================================================================
struct K3S {
    union {
        __half X[256 * TSTR];
        float  C[256 * CSTR];
    };
    __half W[112 * WSTR];
    float  bA[64];
};

__global__ __launch_bounds__(512) void k3_atomsout(
    const float* __restrict__ W_A, const float* __restrict__ b_A,
    float* __restrict__ outA)
{
    extern __shared__ char smem_raw[];
    K3S& S = *reinterpret_cast<K3S*>(smem_raw);
    const int tid  = threadIdx.x;
    const int base = blockIdx.x * 256;

    for (int idx = tid; idx < 256 * TSTR; idx += 512) {
        int m = idx / TSTR, k = idx - m * TSTR;
        int ga = base + m;
        __half v = __float2half(0.f);
        if (ga < N_ATOMS) {
            if      (k < 50)  v = g_AA[(size_t)ga * 50 + k];
            else if (k < 100) v = __float2half(g_PA[(size_t)ga * 50 + (k - 50)]);
        }
        S.X[idx] = v;
    }
    for (int idx = tid; idx < 112 * WSTR; idx += 512) {
        int k = idx / WSTR, n = idx - k * WSTR;
        float w = (k < 100 && n < 50) ? W_A[k * 50 + n] : 0.f;
        S.W[idx] = __float2half(w);
    }
    if (tid < 64) S.bA[tid] = (tid < 50) ? b_A[tid] : 0.f;
    __syncthreads();

    {
        const int mt = tid >> 5;
        wmma::fragment<wmma::accumulator, 16, 16, 16, float> acc[4];
        #pragma unroll
        for (int q = 0; q < 4; q++) wmma::fill_fragment(acc[q], 0.f);
        #pragma unroll
        for (int k = 0; k < 7; k++) {
            wmma::fragment<wmma::matrix_a, 16, 16, 16, __half, wmma::row_major> a;
            wmma::load_matrix_sync(a, S.X + mt * 16 * TSTR + k * 16, TSTR);
            #pragma unroll
            for (int q = 0; q < 4; q++) {
                wmma::fragment<wmma::matrix_b, 16, 16, 16, __half, wmma::row_major> b;
                wmma::load_matrix_sync(b, S.W + k * 16 * WSTR + q * 16, WSTR);
                wmma::mma_sync(acc[q], a, b, acc[q]);
            }
        }
        __syncthreads();
        #pragma unroll
        for (int q = 0; q < 4; q++)
            wmma::store_matrix_sync(S.C + mt * 16 * CSTR + q * 16, acc[q], CSTR,
                                    wmma::mem_row_major);
    }
    __syncthreads();

    for (int idx = tid; idx < 256 * 50; idx += 512) {
        int m = idx / 50, n = idx - m * 50;
        int ga = base + m;
        if (ga < N_ATOMS)
            outA[(size_t)ga * 50 + n] = frelu(S.C[m * CSTR + n] + S.bA[n]);
    }
}

// ============================================================================
extern "C" void kernel_launch(void* const* d_in, const int* in_sizes, int n_in,
                              void* d_out, int out_size) {
    const float* atom_features = (const float*)d_in[0];
    const float* pair_features = (const float*)d_in[1];
    const int*   pair_split    = (const int*)  d_in[2];
    const int*   atom_to_pair  = (const int*)  d_in[3];
    const float* W_AA = (const float*)d_in[4];
    const float* b_AA = (const float*)d_in[5];
    const float* W_PA = (const float*)d_in[6];
    const float* b_PA = (const float*)d_in[7];
    const float* W_A  = (const float*)d_in[8];
    const float* b_A  = (const float*)d_in[9];
    const float* W_AP = (const float*)d_in[10];
    const float* b_AP = (const float*)d_in[11];
    const float* W_PP = (const float*)d_in[12];
    const float* b_PP = (const float*)d_in[13];
    const float* W_P  = (const float*)d_in[14];
    const float* b_P  = (const float*)d_in[15];

    float* outA = (float*)d_out;                        // [100000, 50]
    float* outP = (float*)d_out + (size_t)N_ATOMS * 50; // [1600000, 50]

    cudaFuncSetAttribute(k1_atoms,    cudaFuncAttributeMaxDynamicSharedMemorySize, (int)sizeof(K1S));
    cudaFuncSetAttribute(k2_pairs,    cudaFuncAttributeMaxDynamicSharedMemorySize, (int)sizeof(K2S));
    cudaFuncSetAttribute(k3_atomsout, cudaFuncAttributeMaxDynamicSharedMemorySize, (int)sizeof(K3S));

    k1_atoms<<<(N_ATOMS + 127) / 128, 512, sizeof(K1S)>>>(atom_features, W_AA, b_AA, W_AP);
    k2_pairs<<<K2_GRID, 512, sizeof(K2S)>>>(pair_features, pair_split, atom_to_pair,
                                            W_PA, b_PA, W_PP, b_PP, W_P, b_P, b_AP, outP);
    k3_atomsout<<<(N_ATOMS + 255) / 256, 512, sizeof(K3S)>>>(W_A, b_A, outA);
}

// round 8
// speedup vs baseline: 2.5730x; 1.0671x over previous
#include <cuda_runtime.h>
#include <cuda_fp16.h>
#include <mma.h>

using namespace nvcuda;

#define N_ATOMS  100000
#define N_PAIRS  1600000
#define N_TILES  (N_PAIRS / 256)     // 6250
#define K2_GRID  296

// conflict-free smem strides (half strides mult of 8, float strides mult of 4)
#define TSTR   120   // T stride (halves): 240B/row
#define DSTR   72    // D stride (halves): 144B/row
#define WSTR   72    // Wp stride (halves)
#define WCSTR  136   // Wc stride (halves)
#define PFSTR  16    // pfh stride (halves)
#define CSTR   68    // C stride (floats)
#define AFSTR  88    // k1 A stride (halves)
#define WTSTR  168   // k1 W stride (halves)
#define C1STR  164   // k1 C stride (floats)
#define UVSTR  104   // g_uv row stride in halves (208B = 13 x float4)

// ---------------- scratch (device globals; no allocation allowed) ----------
__device__ __half g_uv [(size_t)N_ATOMS * UVSTR];
__device__ __half g_AA [(size_t)N_ATOMS * 50];
__device__ float  g_PA [(size_t)N_ATOMS * 50];

__device__ __forceinline__ float frelu(float x) { return fmaxf(x, 0.f); }

// ============================================================================
// K1: per-atom GEMM. X = af(128x88pad) @ W(88x168pad) -> AA | u | v. Zero g_PA.
// ============================================================================
struct K1S {
    union {
        struct { __half Af[128 * AFSTR]; __half Wt[80 * WTSTR]; };
        float C[128 * C1STR];
    };
    float bAA[64];
};

__global__ __launch_bounds__(512) void k1_atoms(
    const float* __restrict__ af,
    const float* __restrict__ W_AA, const float* __restrict__ b_AA,
    const float* __restrict__ W_AP)
{
    extern __shared__ char smem_raw[];
    K1S& S = *reinterpret_cast<K1S*>(smem_raw);
    const int tid  = threadIdx.x;
    const int base = blockIdx.x * 128;

    for (int idx = tid; idx < 80 * WTSTR; idx += 512) {
        int d = idx / WTSTR, n = idx - d * WTSTR;
        float w = 0.f;
        if (d < 75) {
            if      (n < 50)  w = W_AA[d * 50 + n];
            else if (n < 100) w = W_AP[d * 50 + (n - 50)];
            else if (n < 150) w = W_AP[(75 + d) * 50 + (n - 100)];
        }
        S.Wt[idx] = __float2half(w);
    }
    for (int idx = tid; idx < 128 * AFSTR; idx += 512) {
        int m = idx / AFSTR, d = idx - m * AFSTR;
        int ga = base + m;
        float v = (ga < N_ATOMS && d < 75) ? af[(size_t)ga * 75 + d] : 0.f;
        S.Af[idx] = __float2half(v);
    }
    if (tid < 50) S.bAA[tid] = b_AA[tid];
    for (int idx = tid; idx < 128 * 50; idx += 512) {
        int ga = base + idx / 50;
        if (ga < N_ATOMS) g_PA[(size_t)ga * 50 + (idx % 50)] = 0.f;
    }
    __syncthreads();

    const int warp = tid >> 5;
    const int mt = warp >> 1;
    const int nb = (warp & 1) * 5;

    wmma::fragment<wmma::accumulator, 16, 16, 16, float> acc[5];
    #pragma unroll
    for (int q = 0; q < 5; q++) wmma::fill_fragment(acc[q], 0.f);
    #pragma unroll
    for (int k = 0; k < 5; k++) {
        wmma::fragment<wmma::matrix_a, 16, 16, 16, __half, wmma::row_major> a;
        wmma::load_matrix_sync(a, S.Af + mt * 16 * AFSTR + k * 16, AFSTR);
        #pragma unroll
        for (int q = 0; q < 5; q++) {
            wmma::fragment<wmma::matrix_b, 16, 16, 16, __half, wmma::row_major> b;
            wmma::load_matrix_sync(b, S.Wt + k * 16 * WTSTR + (nb + q) * 16, WTSTR);
            wmma::mma_sync(acc[q], a, b, acc[q]);
        }
    }
    __syncthreads();
    #pragma unroll
    for (int q = 0; q < 5; q++)
        wmma::store_matrix_sync(S.C + mt * 16 * C1STR + (nb + q) * 16, acc[q], C1STR,
                                wmma::mem_row_major);
    __syncthreads();

    for (int idx = tid; idx < 128 * 25; idx += 512) {
        int m = idx / 25, q = idx - m * 25;
        int ga = base + m;
        if (ga >= N_ATOMS) continue;
        float lo = frelu(S.C[m * C1STR + 2 * q]     + S.bAA[2 * q]);
        float hi = frelu(S.C[m * C1STR + 2 * q + 1] + S.bAA[2 * q + 1]);
        ((__half2*)g_AA)[(size_t)ga * 25 + q] = __floats2half2_rn(lo, hi);
    }
    // (u,v) interleaved, rows padded to 52 half2 (last 2 zero)
    for (int idx = tid; idx < 128 * 52; idx += 512) {
        int m = idx / 52, q = idx - m * 52;
        int ga = base + m;
        if (ga >= N_ATOMS) continue;
        __half2 st = __floats2half2_rn(0.f, 0.f);
        if (q < 50) {
            float u = S.C[m * C1STR + 50 + q];
            float v = S.C[m * C1STR + 100 + q];
            st = __floats2half2_rn(u, v);
        }
        ((__half2*)g_uv)[(size_t)ga * 52 + q] = st;
    }
}

// ============================================================================
// K2: persistent fused pair kernel. 512 threads, 2 blocks/SM.
//  T cols: 0..49 = s, 50..51 = 0 (G writes them as relu(0)=0), 52..101 = PP,
//  102 = 1 (b_P fold), 103..119 = 0.
// ============================================================================
struct K2S {
    union {
        struct { __half T[256 * TSTR]; __half D[128 * DSTR]; };  // 79872 B
        float C[256 * CSTR];                                     // 69632 B
    };
    __half pfh[256 * PFSTR];     // 8192
    __half Wc [16 * WCSTR];      // 4352: cols 0..49 PA, 64..113 PP; row 14 = bias
    __half Wp [112 * WSTR];      // 16128
    float  bAP[64];              // padded; [50..63] = 0 (16B-aligned offset)
    int    ii[256], jj[256], seg[256];
};

__global__ __launch_bounds__(512, 2) void k2_pairs(
    const float* __restrict__ pair_features,
    const int*   __restrict__ pair_split,
    const int*   __restrict__ atom_to_pair,
    const float* __restrict__ W_PA, const float* __restrict__ b_PA,
    const float* __restrict__ W_PP, const float* __restrict__ b_PP,
    const float* __restrict__ W_P,  const float* __restrict__ b_P,
    const float* __restrict__ b_AP,
    float* __restrict__ outP)
{
    extern __shared__ char smem_raw[];
    K2S& S = *reinterpret_cast<K2S*>(smem_raw);
    const int tid  = threadIdx.x;
    const int warp = tid >> 5;
    const __half h0 = __float2half(0.f);

    // ---- stage weights/biases ONCE ----
    for (int idx = tid; idx < 112 * WSTR; idx += 512) {
        int k = idx / WSTR, n = idx - k * WSTR;
        float w = 0.f;
        if (n < 50) {
            if      (k < 50)              w = W_P[k * 50 + n];        // s part
            else if (k >= 52 && k < 102)  w = W_P[(k - 2) * 50 + n];  // PP part
            else if (k == 102)            w = b_P[n];
        }
        S.Wp[idx] = __float2half(w);
    }
    for (int idx = tid; idx < 16 * WCSTR; idx += 512) {
        int d = idx / WCSTR, n = idx - d * WCSTR;
        float w = 0.f;
        if (d < 14) {
            if      (n < 50)             w = W_PA[d * 50 + n];
            else if (n >= 64 && n < 114) w = W_PP[d * 50 + (n - 64)];
        } else if (d == 14) {
            if      (n < 50)             w = b_PA[n];
            else if (n >= 64 && n < 114) w = b_PP[n - 64];
        }
        S.Wc[idx] = __float2half(w);
    }
    if (tid < 64) S.bAP[tid] = (tid < 50) ? b_AP[tid] : 0.f;
    // zero T once
    for (int idx = tid; idx < 256 * TSTR / 2; idx += 512)
        ((__half2*)S.T)[idx] = __floats2half2_rn(0.f, 0.f);

    for (int tile = blockIdx.x; tile < N_TILES; tile += K2_GRID) {
        const int base = tile * 256;
        __syncthreads();   // previous tile's epilogue reads done

        // ---- stage pfh (ones col 14) + indices ----
        for (int idx = tid; idx < 256 * 16; idx += 512) {
            int p = idx >> 4, d = idx & 15;
            float v = (d < 14) ? pair_features[(size_t)(base + p) * 14 + d]
                               : (d == 14 ? 1.f : 0.f);
            S.pfh[idx] = __float2half(v);
        }
        if (tid < 256) {
            int2 p2 = ((const int2*)atom_to_pair)[base + tid];
            S.ii[tid] = p2.x;
            S.jj[tid] = p2.y;
            S.seg[tid] = pair_split[base + tid];
        }
        __syncthreads();

        // ---- W1a: PP -> T[:,52..], W1b h=0: PA -> D ----
        {
            wmma::fragment<wmma::matrix_a, 16, 16, 16, __half, wmma::row_major> a;
            wmma::load_matrix_sync(a, S.pfh + warp * 16 * PFSTR, PFSTR);
            #pragma unroll
            for (int q = 0; q < 4; q++) {
                wmma::fragment<wmma::accumulator, 16, 16, 16, __half> c;
                wmma::fill_fragment(c, h0);
                wmma::fragment<wmma::matrix_b, 16, 16, 16, __half, wmma::row_major> b;
                wmma::load_matrix_sync(b, S.Wc + 64 + 16 * q, WCSTR);
                wmma::mma_sync(c, a, b, c);
                #pragma unroll
                for (int e = 0; e < c.num_elements; e++) c.x[e] = __hmax(c.x[e], h0);
                wmma::store_matrix_sync(S.T + warp * 16 * TSTR + 52 + 16 * q, c, TSTR,
                                        wmma::mem_row_major);
            }
            const int mt = warp >> 1, nq = (warp & 1) * 2;
            wmma::fragment<wmma::matrix_a, 16, 16, 16, __half, wmma::row_major> a2;
            wmma::load_matrix_sync(a2, S.pfh + mt * 16 * PFSTR, PFSTR);
            #pragma unroll
            for (int q = 0; q < 2; q++) {
                wmma::fragment<wmma::accumulator, 16, 16, 16, __half> c;
                wmma::fill_fragment(c, h0);
                wmma::fragment<wmma::matrix_b, 16, 16, 16, __half, wmma::row_major> b;
                wmma::load_matrix_sync(b, S.Wc + 16 * (nq + q), WCSTR);
                wmma::mma_sync(c, a2, b, c);
                #pragma unroll
                for (int e = 0; e < c.num_elements; e++) c.x[e] = __hmax(c.x[e], h0);
                wmma::store_matrix_sync(S.D + mt * 16 * DSTR + 16 * (nq + q), c, DSTR,
                                        wmma::mem_row_major);
            }
        }
        // ---- G: symmetrized AP -> T[:,0:52) via float4 gathers ----
        // thread t<13 of 16 handles k = 4t..4t+3 for its pair
        {
            const int t = tid & 15;
            #pragma unroll
            for (int pass = 0; pass < 8; pass++) {
                const int p = pass * 32 + (tid >> 4);
                if (t < 13) {
                    const int i = S.ii[p], j = S.jj[p];
                    const float4* ri = (const float4*)(g_uv + (size_t)i * UVSTR);
                    const float4* rj = (const float4*)(g_uv + (size_t)j * UVSTR);
                    float4 fa = __ldg(ri + t), fb = __ldg(rj + t);
                    float4 bb = *(const float4*)&S.bAP[4 * t];
                    const __half2* ha = (const __half2*)&fa;
                    const __half2* hb = (const __half2*)&fb;
                    const float*   bp = (const float*)&bb;
                    __half2 out[2];
                    #pragma unroll
                    for (int e = 0; e < 2; e++) {
                        float s[2];
                        #pragma unroll
                        for (int f = 0; f < 2; f++) {
                            __half2 av = ha[2 * e + f], bv = hb[2 * e + f];
                            float b1 = bp[2 * e + f];
                            s[f] = frelu(__low2float(av) + __high2float(bv) + b1)
                                 + frelu(__low2float(bv) + __high2float(av) + b1);
                        }
                        out[e] = __floats2half2_rn(s[0], s[1]);
                    }
                    // single 8B store covering cols 4t..4t+3
                    *(float2*)(S.T + p * TSTR + 4 * t) =
                        make_float2(__uint_as_float(*(unsigned*)&out[0]),
                                    __uint_as_float(*(unsigned*)&out[1]));
                }
            }
        }
        __syncthreads();

        // ---- atomics h=0: rows 0..127, run-compressed ----
        {
            const int col = tid & 63, chunk = tid >> 6;    // 8 chunks x 16 rows
            if (col < 50) {
                const int r0 = chunk * 16;
                float acc = 0.f;
                int cur = S.seg[r0];
                #pragma unroll 4
                for (int r = r0; r < r0 + 16; r++) {
                    float v = __half2float(S.D[r * DSTR + col]);
                    int sg = S.seg[r];
                    if (sg != cur) {
                        atomicAdd(&g_PA[(size_t)cur * 50 + col], acc);
                        acc = 0.f; cur = sg;
                    }
                    acc += v;
                }
                atomicAdd(&g_PA[(size_t)cur * 50 + col], acc);
            }
        }
        __syncthreads();

        // ---- W1b h=1: PA rows 128..255 -> D ----
        {
            const int mt = warp >> 1, nq = (warp & 1) * 2;
            wmma::fragment<wmma::matrix_a, 16, 16, 16, __half, wmma::row_major> a2;
            wmma::load_matrix_sync(a2, S.pfh + (128 + mt * 16) * PFSTR, PFSTR);
            #pragma unroll
            for (int q = 0; q < 2; q++) {
                wmma::fragment<wmma::accumulator, 16, 16, 16, __half> c;
                wmma::fill_fragment(c, h0);
                wmma::fragment<wmma::matrix_b, 16, 16, 16, __half, wmma::row_major> b;
                wmma::load_matrix_sync(b, S.Wc + 16 * (nq + q), WCSTR);
                wmma::mma_sync(c, a2, b, c);
                #pragma unroll
                for (int e = 0; e < c.num_elements; e++) c.x[e] = __hmax(c.x[e], h0);
                wmma::store_matrix_sync(S.D + mt * 16 * DSTR + 16 * (nq + q), c, DSTR,
                                        wmma::mem_row_major);
            }
        }
        __syncthreads();

        // ---- atomics h=1: rows 128..255 ; restore ones col 102 ----
        {
            const int col = tid & 63, chunk = tid >> 6;
            if (col < 50) {
                const int r0 = chunk * 16;
                float acc = 0.f;
                int cur = S.seg[128 + r0];
                #pragma unroll 4
                for (int r = r0; r < r0 + 16; r++) {
                    float v = __half2float(S.D[r * DSTR + col]);
                    int sg = S.seg[128 + r];
                    if (sg != cur) {
                        atomicAdd(&g_PA[(size_t)cur * 50 + col], acc);
                        acc = 0.f; cur = sg;
                    }
                    acc += v;
                }
                atomicAdd(&g_PA[(size_t)cur * 50 + col], acc);
            }
        }
        if (tid < 256) S.T[tid * TSTR + 102] = __float2half(1.f);
        __syncthreads();

        // ---- M: T @ Wp -> C ----
        {
            wmma::fragment<wmma::accumulator, 16, 16, 16, float> acc[4];
            #pragma unroll
            for (int q = 0; q < 4; q++) wmma::fill_fragment(acc[q], 0.f);
            #pragma unroll
            for (int k = 0; k < 7; k++) {
                wmma::fragment<wmma::matrix_a, 16, 16, 16, __half, wmma::row_major> a;
                wmma::load_matrix_sync(a, S.T + warp * 16 * TSTR + k * 16, TSTR);
                #pragma unroll
                for (int q = 0; q < 4; q++) {
                    wmma::fragment<wmma::matrix_b, 16, 16, 16, __half, wmma::row_major> b;
                    wmma::load_matrix_sync(b, S.Wp + k * 16 * WSTR + q * 16, WSTR);
                    wmma::mma_sync(acc[q], a, b, acc[q]);
                }
            }
            __syncthreads();           // all T reads done before C overwrite
            #pragma unroll
            for (int q = 0; q < 4; q++)
                wmma::store_matrix_sync(S.C + warp * 16 * CSTR + q * 16, acc[q], CSTR,
                                        wmma::mem_row_major);
        }
        __syncthreads();

        // ---- E: outP = relu(C) ----
        for (int idx = tid; idx < 256 * 25; idx += 512) {
            int p = idx / 25, q = idx - p * 25;
            float2 c = *(const float2*)&S.C[p * CSTR + 2 * q];
            c.x = frelu(c.x); c.y = frelu(c.y);
            *(float2*)&outP[(size_t)(base + p) * 50 + 2 * q] = c;
        }
        __syncthreads();
        // C overwrote T/D region. Next tile: G rewrites cols 0..51, W1a rewrites
        // 52..115, col 102 reset. Only cols 116..119 need explicit re-zero.
        if (tid < 256) {
            ((__half2*)(S.T + tid * TSTR + 116))[0] = __floats2half2_rn(0.f, 0.f);
            ((__half2*)(S.T + tid * TSTR + 118))[0] = __floats2half2_rn(0.f, 0.f);
        }
    }
}

// ============================================================================
// K3: atom output GEMM. [AA|PA](256x120pad) @ W_A(120x72pad) -> A.
// ============================================================================
struct K3S {
    union {
        __half X[256 * TSTR];
        float  C[256 * CSTR];
    };
    __half W[112 * WSTR];
    float  bA[64];
};

__global__ __launch_bounds__(512) void k3_atomsout(
    const float* __restrict__ W_A, const float* __restrict__ b_A,
    float* __restrict__ outA)
{
    extern __shared__ char smem_raw[];
    K3S& S = *reinterpret_cast<K3S*>(smem_raw);
    const int tid  = threadIdx.x;
    const int base = blockIdx.x * 256;

    for (int idx = tid; idx < 256 * TSTR; idx += 512) {
        int m = idx / TSTR, k = idx - m * TSTR;
        int ga = base + m;
        __half v = __float2half(0.f);
        if (ga < N_ATOMS) {
            if      (k < 50)  v = g_AA[(size_t)ga * 50 + k];
            else if (k < 100) v = __float2half(g_PA[(size_t)ga * 50 + (k - 50)]);
        }
        S.X[idx] = v;
    }
    for (int idx = tid; idx < 112 * WSTR; idx += 512) {
        int k = idx / WSTR, n = idx - k * WSTR;
        float w = (k < 100 && n < 50) ? W_A[k * 50 + n] : 0.f;
        S.W[idx] = __float2half(w);
    }
    if (tid < 64) S.bA[tid] = (tid < 50) ? b_A[tid] : 0.f;
    __syncthreads();

    {
        const int mt = tid >> 5;
        wmma::fragment<wmma::accumulator, 16, 16, 16, float> acc[4];
        #pragma unroll
        for (int q = 0; q < 4; q++) wmma::fill_fragment(acc[q], 0.f);
        #pragma unroll
        for (int k = 0; k < 7; k++) {
            wmma::fragment<wmma::matrix_a, 16, 16, 16, __half, wmma::row_major> a;
            wmma::load_matrix_sync(a, S.X + mt * 16 * TSTR + k * 16, TSTR);
            #pragma unroll
            for (int q = 0; q < 4; q++) {
                wmma::fragment<wmma::matrix_b, 16, 16, 16, __half, wmma::row_major> b;
                wmma::load_matrix_sync(b, S.W + k * 16 * WSTR + q * 16, WSTR);
                wmma::mma_sync(acc[q], a, b, acc[q]);
            }
        }
        __syncthreads();
        #pragma unroll
        for (int q = 0; q < 4; q++)
            wmma::store_matrix_sync(S.C + mt * 16 * CSTR + q * 16, acc[q], CSTR,
                                    wmma::mem_row_major);
    }
    __syncthreads();

    for (int idx = tid; idx < 256 * 50; idx += 512) {
        int m = idx / 50, n = idx - m * 50;
        int ga = base + m;
        if (ga < N_ATOMS)
            outA[(size_t)ga * 50 + n] = frelu(S.C[m * CSTR + n] + S.bA[n]);
    }
}

// ============================================================================
extern "C" void kernel_launch(void* const* d_in, const int* in_sizes, int n_in,
                              void* d_out, int out_size) {
    const float* atom_features = (const float*)d_in[0];
    const float* pair_features = (const float*)d_in[1];
    const int*   pair_split    = (const int*)  d_in[2];
    const int*   atom_to_pair  = (const int*)  d_in[3];
    const float* W_AA = (const float*)d_in[4];
    const float* b_AA = (const float*)d_in[5];
    const float* W_PA = (const float*)d_in[6];
    const float* b_PA = (const float*)d_in[7];
    const float* W_A  = (const float*)d_in[8];
    const float* b_A  = (const float*)d_in[9];
    const float* W_AP = (const float*)d_in[10];
    const float* b_AP = (const float*)d_in[11];
    const float* W_PP = (const float*)d_in[12];
    const float* b_PP = (const float*)d_in[13];
    const float* W_P  = (const float*)d_in[14];
    const float* b_P  = (const float*)d_in[15];

    float* outA = (float*)d_out;                        // [100000, 50]
    float* outP = (float*)d_out + (size_t)N_ATOMS * 50; // [1600000, 50]

    cudaFuncSetAttribute(k1_atoms,    cudaFuncAttributeMaxDynamicSharedMemorySize, (int)sizeof(K1S));
    cudaFuncSetAttribute(k2_pairs,    cudaFuncAttributeMaxDynamicSharedMemorySize, (int)sizeof(K2S));
    cudaFuncSetAttribute(k3_atomsout, cudaFuncAttributeMaxDynamicSharedMemorySize, (int)sizeof(K3S));

    k1_atoms<<<(N_ATOMS + 127) / 128, 512, sizeof(K1S)>>>(atom_features, W_AA, b_AA, W_AP);
    k2_pairs<<<K2_GRID, 512, sizeof(K2S)>>>(pair_features, pair_split, atom_to_pair,
                                            W_PA, b_PA, W_PP, b_PP, W_P, b_P, b_AP, outP);
    k3_atomsout<<<(N_ATOMS + 255) / 256, 512, sizeof(K3S)>>>(W_A, b_A, outA);
}

// round 12
// speedup vs baseline: 2.7690x; 1.0762x over previous
#include <cuda_runtime.h>
#include <cuda_fp16.h>
#include <mma.h>

using namespace nvcuda;

#define N_ATOMS  100000
#define N_PAIRS  1600000
#define N_TILES  (N_PAIRS / 256)     // 6250
#define K2_GRID  296

// smem strides (half strides mult of 8, float strides mult of 4)
#define TSTR   120   // T stride (halves): 240B/row -> distinct bank phases
#define DSTR   72    // D stride (halves)
#define WSTR   72    // Wp stride (halves)
#define WCSTR  136   // Wc stride (halves)
#define PFSTR  16    // pfh stride (halves)
#define CSTR   64    // C stride (floats): 256B/row; 4 full 16-wide tiles fit
#define AFSTR  88    // k1 A stride (halves)
#define WTSTR  168   // k1 W stride (halves)
#define C1STR  164   // k1 C stride (floats)
#define UVSTR  104   // g_uv row stride in halves (208B = 13 x float4)

#define T_BYTES   (256 * TSTR * 2)          // 61440
#define D_BYTES   (128 * DSTR * 2)          // 18432
#define BUF_BYTES (T_BYTES + D_BYTES)       // 79872
#define C_BYTES   (256 * CSTR * 4)          // 65536 (covers T + 4096B of dead D)
#define PF32_OFF  C_BYTES                   // pf32 @65536..79872 (14336B) - no C overlap

// ---------------- scratch (device globals; no allocation allowed) ----------
__device__ __half g_uv [(size_t)N_ATOMS * UVSTR];
__device__ __half g_AA [(size_t)N_ATOMS * 50];
__device__ float  g_PA [(size_t)N_ATOMS * 50];

__device__ __forceinline__ float frelu(float x) { return fmaxf(x, 0.f); }

__device__ __forceinline__ void cp16(unsigned int smem_dst, const void* gmem_src) {
    asm volatile("cp.async.ca.shared.global [%0], [%1], 16;\n"
                 :: "r"(smem_dst), "l"(gmem_src));
}
#define CP_COMMIT() asm volatile("cp.async.commit_group;\n" ::: "memory")
#define CP_WAIT0()  asm volatile("cp.async.wait_group 0;\n" ::: "memory")

// ============================================================================
// K1: per-atom GEMM. X = af(128x88pad) @ W(88x168pad) -> AA | u | v. Zero g_PA.
// ============================================================================
struct K1S {
    __align__(16) char buf[128 * C1STR * 4];  // Af+Wt overlay C (raw bytes)
    float bAA[64];
};

__global__ __launch_bounds__(512) void k1_atoms(
    const float* __restrict__ af,
    const float* __restrict__ W_AA, const float* __restrict__ b_AA,
    const float* __restrict__ W_AP)
{
    extern __shared__ char smem_raw[];
    K1S& S = *reinterpret_cast<K1S*>(smem_raw);
    __half* Af = (__half*)S.buf;                          // 22528 B
    __half* Wt = (__half*)(S.buf + 128 * AFSTR * 2);      // 26880 B
    float*  C  = (float*)S.buf;                           // 83968 B
    const int tid  = threadIdx.x;
    const int warp = tid >> 5;
    const int lane = tid & 31;
    const int base = blockIdx.x * 128;

    #pragma unroll
    for (int rr = 0; rr < 5; rr++) {
        const int d = warp * 5 + rr;
        const bool dok = d < 75;
        for (int c = lane; c < WTSTR; c += 32) {
            float w = 0.f;
            if (dok && c < 150) {
                if      (c < 50)  w = W_AA[d * 50 + c];
                else if (c < 100) w = W_AP[d * 50 + (c - 50)];
                else              w = W_AP[(75 + d) * 50 + (c - 100)];
            }
            Wt[d * WTSTR + c] = __float2half(w);
        }
    }
    for (int r = warp; r < 128; r += 16) {
        const int ga = base + r;
        for (int c = lane; c < AFSTR; c += 32) {
            float v = (ga < N_ATOMS && c < 75) ? af[(size_t)ga * 75 + c] : 0.f;
            Af[r * AFSTR + c] = __float2half(v);
        }
    }
    if (tid < 50) S.bAA[tid] = b_AA[tid];
    for (int r = warp; r < 128; r += 16) {
        const int ga = base + r;
        if (ga < N_ATOMS && lane < 25)
            ((float2*)(g_PA + (size_t)ga * 50))[lane] = make_float2(0.f, 0.f);
    }
    __syncthreads();

    const int mt = warp >> 1;
    const int nb = (warp & 1) * 5;

    wmma::fragment<wmma::accumulator, 16, 16, 16, float> acc[5];
    #pragma unroll
    for (int q = 0; q < 5; q++) wmma::fill_fragment(acc[q], 0.f);
    #pragma unroll
    for (int k = 0; k < 5; k++) {
        wmma::fragment<wmma::matrix_a, 16, 16, 16, __half, wmma::row_major> a;
        wmma::load_matrix_sync(a, Af + mt * 16 * AFSTR + k * 16, AFSTR);
        #pragma unroll
        for (int q = 0; q < 5; q++) {
            wmma::fragment<wmma::matrix_b, 16, 16, 16, __half, wmma::row_major> b;
            wmma::load_matrix_sync(b, Wt + k * 16 * WTSTR + (nb + q) * 16, WTSTR);
            wmma::mma_sync(acc[q], a, b, acc[q]);
        }
    }
    __syncthreads();
    #pragma unroll
    for (int q = 0; q < 5; q++)
        wmma::store_matrix_sync(C + mt * 16 * C1STR + (nb + q) * 16, acc[q], C1STR,
                                wmma::mem_row_major);
    __syncthreads();

    for (int r = warp; r < 128; r += 16) {
        const int ga = base + r;
        if (ga >= N_ATOMS) continue;
        if (lane < 25) {
            float lo = frelu(C[r * C1STR + 2 * lane]     + S.bAA[2 * lane]);
            float hi = frelu(C[r * C1STR + 2 * lane + 1] + S.bAA[2 * lane + 1]);
            ((__half2*)g_AA)[(size_t)ga * 25 + lane] = __floats2half2_rn(lo, hi);
        }
        for (int q = lane; q < 52; q += 32) {
            __half2 st = __floats2half2_rn(0.f, 0.f);
            if (q < 50)
                st = __floats2half2_rn(C[r * C1STR + 50 + q],
                                       C[r * C1STR + 100 + q]);
            ((__half2*)g_uv)[(size_t)ga * 52 + q] = st;
        }
    }
}

// ============================================================================
// K2: persistent fused pair kernel. 512 threads, 2 blocks/SM.
//  buf: T(halves)@0 (61440B), D@61440 (18432B), C(floats)@0 (65536B, covers
//  T + first 4096B of dead D), pf32 prefetch target @65536 (14336B, disjoint
//  from C; D is dead when prefetch lands).
// ============================================================================
struct K2S {
    __align__(16) char buf[BUF_BYTES];       // 79872
    __align__(16) __half pfh[256 * PFSTR];   // 8192
    __align__(16) __half Wc [16 * WCSTR];    // 4352
    __align__(16) __half Wp [112 * WSTR];    // 16128
    __align__(16) float  bAP[64];
    __align__(16) int2   ij2[256];           // 2048 (cp.async raw target)
    __align__(16) int    seg[256];           // 1024 (cp.async raw target)
};

__global__ __launch_bounds__(512, 2) void k2_pairs(
    const float* __restrict__ pair_features,
    const int*   __restrict__ pair_split,
    const int*   __restrict__ atom_to_pair,
    const float* __restrict__ W_PA, const float* __restrict__ b_PA,
    const float* __restrict__ W_PP, const float* __restrict__ b_PP,
    const float* __restrict__ W_P,  const float* __restrict__ b_P,
    const float* __restrict__ b_AP,
    float* __restrict__ outP)
{
    extern __shared__ char smem_raw[];
    K2S& S = *reinterpret_cast<K2S*>(smem_raw);
    __half* T    = (__half*)S.buf;
    __half* D    = (__half*)(S.buf + T_BYTES);
    float*  pf32 = (float*)(S.buf + PF32_OFF);
    float*  C    = (float*)S.buf;
    const int tid  = threadIdx.x;
    const int warp = tid >> 5;
    const __half h0 = __float2half(0.f);

    // ---- stage weights/biases ONCE ----
    for (int idx = tid; idx < 112 * WSTR; idx += 512) {
        int k = idx / WSTR, n = idx - k * WSTR;
        float w = 0.f;
        if (n < 50) {
            if      (k < 50)              w = W_P[k * 50 + n];        // s part
            else if (k >= 52 && k < 102)  w = W_P[(k - 2) * 50 + n];  // PP part
            else if (k == 102)            w = b_P[n];
        }
        S.Wp[idx] = __float2half(w);
    }
    for (int idx = tid; idx < 16 * WCSTR; idx += 512) {
        int d = idx / WCSTR, n = idx - d * WCSTR;
        float w = 0.f;
        if (d < 14) {
            if      (n < 50)             w = W_PA[d * 50 + n];
            else if (n >= 64 && n < 114) w = W_PP[d * 50 + (n - 64)];
        } else if (d == 14) {
            if      (n < 50)             w = b_PA[n];
            else if (n >= 64 && n < 114) w = b_PP[n - 64];
        }
        S.Wc[idx] = __float2half(w);
    }
    if (tid < 64) S.bAP[tid] = (tid < 50) ? b_AP[tid] : 0.f;
    // zero T once
    for (int idx = tid; idx < 256 * TSTR / 2; idx += 512)
        ((__half2*)T)[idx] = __floats2half2_rn(0.f, 0.f);

    // ---- prologue prefetch for first tile ----
    {
        const int nbase = blockIdx.x * 256;
        unsigned int d0 = (unsigned int)__cvta_generic_to_shared(pf32);
        const char* s0 = (const char*)(pair_features + (size_t)nbase * 14);
        for (int c = tid; c < 896; c += 512) cp16(d0 + c * 16, s0 + c * 16);
        unsigned int d1 = (unsigned int)__cvta_generic_to_shared(S.ij2);
        const char* s1 = (const char*)(atom_to_pair + (size_t)nbase * 2);
        if (tid < 128) cp16(d1 + tid * 16, s1 + tid * 16);
        unsigned int d2 = (unsigned int)__cvta_generic_to_shared(S.seg);
        const char* s2 = (const char*)(pair_split + nbase);
        if (tid < 64) cp16(d2 + tid * 16, s2 + tid * 16);
        CP_COMMIT();
        CP_WAIT0();
    }

    for (int tile = blockIdx.x; tile < N_TILES; tile += K2_GRID) {
        const int base = tile * 256;
        __syncthreads();   // prefetch visible / previous tile fully done

        // ---- stage: pfh <- cvt(pf32)  (pure smem, no DRAM latency) ----
        {
            const int p = tid >> 1, h = tid & 1;
            const float* src = &pf32[p * 14];
            __half2* dst = (__half2*)(S.pfh + p * PFSTR) + h * 4;
            if (h == 0) {
                dst[0] = __floats2half2_rn(src[0],  src[1]);
                dst[1] = __floats2half2_rn(src[2],  src[3]);
                dst[2] = __floats2half2_rn(src[4],  src[5]);
                dst[3] = __floats2half2_rn(src[6],  src[7]);
            } else {
                dst[0] = __floats2half2_rn(src[8],  src[9]);
                dst[1] = __floats2half2_rn(src[10], src[11]);
                dst[2] = __floats2half2_rn(src[12], src[13]);
                dst[3] = __floats2half2_rn(1.f, 0.f);      // ones col 14, pad 15
            }
        }
        __syncthreads();

        // ---- W1a: PP -> T[:,52..], W1b h=0: PA -> D ----
        {
            wmma::fragment<wmma::matrix_a, 16, 16, 16, __half, wmma::row_major> a;
            wmma::load_matrix_sync(a, S.pfh + warp * 16 * PFSTR, PFSTR);
            #pragma unroll
            for (int q = 0; q < 4; q++) {
                wmma::fragment<wmma::accumulator, 16, 16, 16, __half> c;
                wmma::fill_fragment(c, h0);
                wmma::fragment<wmma::matrix_b, 16, 16, 16, __half, wmma::row_major> b;
                wmma::load_matrix_sync(b, S.Wc + 64 + 16 * q, WCSTR);
                wmma::mma_sync(c, a, b, c);
                #pragma unroll
                for (int e = 0; e < c.num_elements; e++) c.x[e] = __hmax(c.x[e], h0);
                wmma::store_matrix_sync(T + warp * 16 * TSTR + 52 + 16 * q, c, TSTR,
                                        wmma::mem_row_major);
            }
            const int mt = warp >> 1, nq = (warp & 1) * 2;
            wmma::fragment<wmma::matrix_a, 16, 16, 16, __half, wmma::row_major> a2;
            wmma::load_matrix_sync(a2, S.pfh + mt * 16 * PFSTR, PFSTR);
            #pragma unroll
            for (int q = 0; q < 2; q++) {
                wmma::fragment<wmma::accumulator, 16, 16, 16, __half> c;
                wmma::fill_fragment(c, h0);
                wmma::fragment<wmma::matrix_b, 16, 16, 16, __half, wmma::row_major> b;
                wmma::load_matrix_sync(b, S.Wc + 16 * (nq + q), WCSTR);
                wmma::mma_sync(c, a2, b, c);
                #pragma unroll
                for (int e = 0; e < c.num_elements; e++) c.x[e] = __hmax(c.x[e], h0);
                wmma::store_matrix_sync(D + mt * 16 * DSTR + 16 * (nq + q), c, DSTR,
                                        wmma::mem_row_major);
            }
        }
        // ---- G: symmetrized AP -> T[:,0:52) via float4 gathers ----
        {
            const int t = tid & 15;
            #pragma unroll
            for (int pass = 0; pass < 8; pass++) {
                const int p = pass * 32 + (tid >> 4);
                if (t < 13) {
                    const int2 pij = S.ij2[p];
                    const float4* ri = (const float4*)(g_uv + (size_t)pij.x * UVSTR);
                    const float4* rj = (const float4*)(g_uv + (size_t)pij.y * UVSTR);
                    float4 fa = __ldg(ri + t), fb = __ldg(rj + t);
                    float4 bb = *(const float4*)&S.bAP[4 * t];
                    const __half2* ha = (const __half2*)&fa;
                    const __half2* hb = (const __half2*)&fb;
                    const float*   bp = (const float*)&bb;
                    __half2 out[2];
                    #pragma unroll
                    for (int e = 0; e < 2; e++) {
                        float s[2];
                        #pragma unroll
                        for (int f = 0; f < 2; f++) {
                            __half2 av = ha[2 * e + f], bv = hb[2 * e + f];
                            float b1 = bp[2 * e + f];
                            s[f] = frelu(__low2float(av) + __high2float(bv) + b1)
                                 + frelu(__low2float(bv) + __high2float(av) + b1);
                        }
                        out[e] = __floats2half2_rn(s[0], s[1]);
                    }
                    *(float2*)(T + p * TSTR + 4 * t) =
                        make_float2(__uint_as_float(*(unsigned*)&out[0]),
                                    __uint_as_float(*(unsigned*)&out[1]));
                }
            }
        }
        __syncthreads();

        // ---- atomics h=0: rows 0..127, run-compressed ----
        {
            const int col = tid & 63, chunk = tid >> 6;    // 8 chunks x 16 rows
            if (col < 50) {
                const int r0 = chunk * 16;
                float acc = 0.f;
                int cur = S.seg[r0];
                #pragma unroll 4
                for (int r = r0; r < r0 + 16; r++) {
                    float v = __half2float(D[r * DSTR + col]);
                    int sg = S.seg[r];
                    if (sg != cur) {
                        atomicAdd(&g_PA[(size_t)cur * 50 + col], acc);
                        acc = 0.f; cur = sg;
                    }
                    acc += v;
                }
                atomicAdd(&g_PA[(size_t)cur * 50 + col], acc);
            }
        }
        __syncthreads();

        // ---- W1b h=1: PA rows 128..255 -> D ----
        {
            const int mt = warp >> 1, nq = (warp & 1) * 2;
            wmma::fragment<wmma::matrix_a, 16, 16, 16, __half, wmma::row_major> a2;
            wmma::load_matrix_sync(a2, S.pfh + (128 + mt * 16) * PFSTR, PFSTR);
            #pragma unroll
            for (int q = 0; q < 2; q++) {
                wmma::fragment<wmma::accumulator, 16, 16, 16, __half> c;
                wmma::fill_fragment(c, h0);
                wmma::fragment<wmma::matrix_b, 16, 16, 16, __half, wmma::row_major> b;
                wmma::load_matrix_sync(b, S.Wc + 16 * (nq + q), WCSTR);
                wmma::mma_sync(c, a2, b, c);
                #pragma unroll
                for (int e = 0; e < c.num_elements; e++) c.x[e] = __hmax(c.x[e], h0);
                wmma::store_matrix_sync(D + mt * 16 * DSTR + 16 * (nq + q), c, DSTR,
                                        wmma::mem_row_major);
            }
        }
        __syncthreads();

        // ---- atomics h=1: rows 128..255 ; restore ones col 102 ----
        {
            const int col = tid & 63, chunk = tid >> 6;
            if (col < 50) {
                const int r0 = chunk * 16;
                float acc = 0.f;
                int cur = S.seg[128 + r0];
                #pragma unroll 4
                for (int r = r0; r < r0 + 16; r++) {
                    float v = __half2float(D[r * DSTR + col]);
                    int sg = S.seg[128 + r];
                    if (sg != cur) {
                        atomicAdd(&g_PA[(size_t)cur * 50 + col], acc);
                        acc = 0.f; cur = sg;
                    }
                    acc += v;
                }
                atomicAdd(&g_PA[(size_t)cur * 50 + col], acc);
            }
        }
        if (tid < 256) T[tid * TSTR + 102] = __float2half(1.f);
        __syncthreads();
        // D, ij2, seg now dead -> prefetch NEXT tile (overlaps M + E).
        // pf32 region [65536,79872) is disjoint from C [0,65536).
        {
            const int ntile = tile + K2_GRID;
            if (ntile < N_TILES) {
                const int nbase = ntile * 256;
                unsigned int d0 = (unsigned int)__cvta_generic_to_shared(pf32);
                const char* s0 = (const char*)(pair_features + (size_t)nbase * 14);
                for (int c = tid; c < 896; c += 512) cp16(d0 + c * 16, s0 + c * 16);
                unsigned int d1 = (unsigned int)__cvta_generic_to_shared(S.ij2);
                const char* s1 = (const char*)(atom_to_pair + (size_t)nbase * 2);
                if (tid < 128) cp16(d1 + tid * 16, s1 + tid * 16);
                unsigned int d2 = (unsigned int)__cvta_generic_to_shared(S.seg);
                const char* s2 = (const char*)(pair_split + nbase);
                if (tid < 64) cp16(d2 + tid * 16, s2 + tid * 16);
            }
            CP_COMMIT();
        }

        // ---- M: T @ Wp -> C (CSTR=64: 4 full tiles per row, no overflow) ----
        {
            wmma::fragment<wmma::accumulator, 16, 16, 16, float> acc[4];
            #pragma unroll
            for (int q = 0; q < 4; q++) wmma::fill_fragment(acc[q], 0.f);
            #pragma unroll
            for (int k = 0; k < 7; k++) {
                wmma::fragment<wmma::matrix_a, 16, 16, 16, __half, wmma::row_major> a;
                wmma::load_matrix_sync(a, T + warp * 16 * TSTR + k * 16, TSTR);
                #pragma unroll
                for (int q = 0; q < 4; q++) {
                    wmma::fragment<wmma::matrix_b, 16, 16, 16, __half, wmma::row_major> b;
                    wmma::load_matrix_sync(b, S.Wp + k * 16 * WSTR + q * 16, WSTR);
                    wmma::mma_sync(acc[q], a, b, acc[q]);
                }
            }
            __syncthreads();           // all T reads done before C overwrite
            #pragma unroll
            for (int q = 0; q < 4; q++)
                wmma::store_matrix_sync(C + warp * 16 * CSTR + q * 16, acc[q], CSTR,
                                        wmma::mem_row_major);
        }
        __syncthreads();

        // ---- E: outP = relu(C) ----
        for (int idx = tid; idx < 256 * 25; idx += 512) {
            int p = idx / 25, q = idx - p * 25;
            float2 c = *(const float2*)&C[p * CSTR + 2 * q];
            c.x = frelu(c.x); c.y = frelu(c.y);
            *(float2*)&outP[(size_t)(base + p) * 50 + 2 * q] = c;
        }
        CP_WAIT0();                    // prefetch landed before loop-top barrier
    }
}

// ============================================================================
// K3: atom output GEMM. [AA|PA](256x120pad) @ W_A(120x72pad) -> A.
// ============================================================================
struct K3S {
    __align__(16) char buf[256 * CSTR * 4];   // 65536: X (61440) overlay C (65536)
    __half W[112 * WSTR];
    float  bA[64];
};

__global__ __launch_bounds__(512) void k3_atomsout(
    const float* __restrict__ W_A, const float* __restrict__ b_A,
    float* __restrict__ outA)
{
    extern __shared__ char smem_raw[];
    K3S& S = *reinterpret_cast<K3S*>(smem_raw);
    __half* X = (__half*)S.buf;
    float*  C = (float*)S.buf;
    const int tid  = threadIdx.x;
    const int warp = tid >> 5;
    const int lane = tid & 31;
    const int base = blockIdx.x * 256;
    const __half hz = __float2half(0.f);

    for (int r = warp; r < 256; r += 16) {
        const int ga = base + r;
        #pragma unroll
        for (int ci = 0; ci < 4; ci++) {
            const int c = lane + ci * 32;
            if (c >= TSTR) continue;
            __half v = hz;
            if (ga < N_ATOMS) {
                if      (c < 50)  v = g_AA[(size_t)ga * 50 + c];
                else if (c < 100) v = __float2half(g_PA[(size_t)ga * 50 + (c - 50)]);
            }
            X[r * TSTR + c] = v;
        }
    }
    #pragma unroll
    for (int rr = 0; rr < 7; rr++) {
        const int k = warp * 7 + rr;
        #pragma unroll
        for (int ci = 0; ci < 3; ci++) {
            const int c = lane + ci * 32;
            if (c >= WSTR) continue;
            float w = (k < 100 && c < 50) ? W_A[k * 50 + c] : 0.f;
            S.W[k * WSTR + c] = __float2half(w);
        }
    }
    if (tid < 64) S.bA[tid] = (tid < 50) ? b_A[tid] : 0.f;
    __syncthreads();

    {
        const int mt = warp;
        wmma::fragment<wmma::accumulator, 16, 16, 16, float> acc[4];
        #pragma unroll
        for (int q = 0; q < 4; q++) wmma::fill_fragment(acc[q], 0.f);
        #pragma unroll
        for (int k = 0; k < 7; k++) {
            wmma::fragment<wmma::matrix_a, 16, 16, 16, __half, wmma::row_major> a;
            wmma::load_matrix_sync(a, X + mt * 16 * TSTR + k * 16, TSTR);
            #pragma unroll
            for (int q = 0; q < 4; q++) {
                wmma::fragment<wmma::matrix_b, 16, 16, 16, __half, wmma::row_major> b;
                wmma::load_matrix_sync(b, S.W + k * 16 * WSTR + q * 16, WSTR);
                wmma::mma_sync(acc[q], a, b, acc[q]);
            }
        }
        __syncthreads();
        #pragma unroll
        for (int q = 0; q < 4; q++)
            wmma::store_matrix_sync(C + mt * 16 * CSTR + q * 16, acc[q], CSTR,
                                    wmma::mem_row_major);
    }
    __syncthreads();

    for (int r = warp; r < 256; r += 16) {
        const int ga = base + r;
        if (ga >= N_ATOMS || lane >= 25) continue;
        float lo = frelu(C[r * CSTR + 2 * lane]     + S.bA[2 * lane]);
        float hi = frelu(C[r * CSTR + 2 * lane + 1] + S.bA[2 * lane + 1]);
        *(float2*)&outA[(size_t)ga * 50 + 2 * lane] = make_float2(lo, hi);
    }
}

// ============================================================================
extern "C" void kernel_launch(void* const* d_in, const int* in_sizes, int n_in,
                              void* d_out, int out_size) {
    const float* atom_features = (const float*)d_in[0];
    const float* pair_features = (const float*)d_in[1];
    const int*   pair_split    = (const int*)  d_in[2];
    const int*   atom_to_pair  = (const int*)  d_in[3];
    const float* W_AA = (const float*)d_in[4];
    const float* b_AA = (const float*)d_in[5];
    const float* W_PA = (const float*)d_in[6];
    const float* b_PA = (const float*)d_in[7];
    const float* W_A  = (const float*)d_in[8];
    const float* b_A  = (const float*)d_in[9];
    const float* W_AP = (const float*)d_in[10];
    const float* b_AP = (const float*)d_in[11];
    const float* W_PP = (const float*)d_in[12];
    const float* b_PP = (const float*)d_in[13];
    const float* W_P  = (const float*)d_in[14];
    const float* b_P  = (const float*)d_in[15];

    float* outA = (float*)d_out;                        // [100000, 50]
    float* outP = (float*)d_out + (size_t)N_ATOMS * 50; // [1600000, 50]

    cudaFuncSetAttribute(k1_atoms,    cudaFuncAttributeMaxDynamicSharedMemorySize, (int)sizeof(K1S));
    cudaFuncSetAttribute(k2_pairs,    cudaFuncAttributeMaxDynamicSharedMemorySize, (int)sizeof(K2S));
    cudaFuncSetAttribute(k3_atomsout, cudaFuncAttributeMaxDynamicSharedMemorySize, (int)sizeof(K3S));

    k1_atoms<<<(N_ATOMS + 127) / 128, 512, sizeof(K1S)>>>(atom_features, W_AA, b_AA, W_AP);
    k2_pairs<<<K2_GRID, 512, sizeof(K2S)>>>(pair_features, pair_split, atom_to_pair,
                                            W_PA, b_PA, W_PP, b_PP, W_P, b_P, b_AP, outP);
    k3_atomsout<<<(N_ATOMS + 255) / 256, 512, sizeof(K3S)>>>(W_A, b_A, outA);
}